// round 12
// baseline (speedup 1.0000x reference)
#include <cuda_runtime.h>
#include <cuda_fp16.h>
#include <cstdint>

// ---------------------------------------------------------------------------
// DeepSeek MLA block on GB300 — mma.sync fp16 GEMMs, v10.
// q/k path: fp16-pair 3-term split. Additive paths: 1-term fp16.
// v10: 256x128 CTA tiles (512 thr, warp tile 64x32) to halve smem-crossbar
//      bytes per FLOP (was co-binding with the tensor pipe at ~62% util).
// ---------------------------------------------------------------------------

#define CB 2
#define CT 1024
#define CD 2048
#define CH 16
#define CNOPE 128
#define CROPE 64
#define CQKD 192
#define CQLORA 1536
#define CKVLORA 512
#define CVHD 128
#define CINTER 8192
#define CM (CB*CT)
#define NQKVA (CQLORA + CKVLORA + CROPE)   // 2112

// ------------------------------- PTX helpers -------------------------------
__device__ __forceinline__ uint32_t smem_u32(const void* p) {
    uint32_t a;
    asm("{ .reg .u64 t; cvta.to.shared.u64 t, %1; cvt.u32.u64 %0, t; }" : "=r"(a) : "l"(p));
    return a;
}
#define SW128(o) ((o) ^ (((o) >> 3) & 0x70))

__device__ __forceinline__ void cpa16(uint32_t s, const void* g, int sz) {
    asm volatile("cp.async.cg.shared.global [%0], [%1], 16, %2;"
                 :: "r"(s), "l"(g), "r"(sz));
}
__device__ __forceinline__ void cp_commit() {
    asm volatile("cp.async.commit_group;" ::: "memory");
}
template <int N> __device__ __forceinline__ void cp_wait() {
    asm volatile("cp.async.wait_group %0;" :: "n"(N) : "memory");
}
__device__ __forceinline__ void ldsm_x4(uint32_t* r, uint32_t a) {
    asm volatile("ldmatrix.sync.aligned.m8n8.x4.shared.b16 {%0,%1,%2,%3}, [%4];"
        : "=r"(r[0]), "=r"(r[1]), "=r"(r[2]), "=r"(r[3]) : "r"(a));
}
__device__ __forceinline__ void mma_f16(float* d, const uint32_t* a, const uint32_t* b) {
    asm volatile(
        "mma.sync.aligned.m16n8k16.row.col.f32.f16.f16.f32 "
        "{%0,%1,%2,%3}, {%4,%5,%6,%7}, {%8,%9}, {%0,%1,%2,%3};"
        : "+f"(d[0]), "+f"(d[1]), "+f"(d[2]), "+f"(d[3])
        : "r"(a[0]), "r"(a[1]), "r"(a[2]), "r"(a[3]), "r"(b[0]), "r"(b[1]));
}

// ------------------------- scratch (device globals) ------------------------
__device__ float g_qkva[(long long)CM*NQKVA];
__device__ float g_q   [(long long)CM*CH*CQKD];
__device__ float g_kv  [(long long)CM*CH*(CNOPE+CVHD)];
__device__ float g_sc  [(long long)CB*CH*CT*CT];
__device__ float g_x2  [(long long)CM*CD];

// fp16 operand buffers
__device__ __half f_hH [(long long)CM*CD],        f_hL [(long long)CM*CD];
__device__ __half f_qaH[(long long)CM*CQLORA],    f_qaL[(long long)CM*CQLORA];
__device__ __half f_kvnH[(long long)CM*CKVLORA],  f_kvnL[(long long)CM*CKVLORA];
__device__ __half f_qfH[(long long)CB*CH*CT*CQKD], f_qfL[(long long)CB*CH*CT*CQKD];
__device__ __half f_kfH[(long long)CB*CH*CT*CQKD], f_kfL[(long long)CB*CH*CT*CQKD];
__device__ __half f_vT [(long long)CB*CH*CVHD*CT];
__device__ __half f_at [(long long)CB*CH*CT*CT];
__device__ __half f_y2 [(long long)CM*CD];
__device__ __half f_h2 [(long long)CM*CD];
__device__ __half f_gs [(long long)CM*CINTER];
// weights
__device__ __half f_wqkaH[(long long)NQKVA*CD],   f_wqkaL[(long long)NQKVA*CD];
__device__ __half f_wqbH[(long long)CH*CQKD*CQLORA], f_wqbL[(long long)CH*CQKD*CQLORA];
__device__ __half f_wkbH[(long long)CH*256*CKVLORA], f_wkbL[(long long)CH*256*CKVLORA];
__device__ __half f_wo [(long long)CD*CD];
__device__ __half f_w13[(long long)2*CINTER*CD];   // interleaved: row 2j=w1_j, 2j+1=w3_j
__device__ __half f_w2 [(long long)CD*CINTER];

// ------------------------------- split helpers -----------------------------
__device__ __forceinline__ void split1h(float v, __half& h, __half& l) {
    h = __float2half_rn(v);
    l = __float2half_rn(v - __half2float(h));
}

__global__ __launch_bounds__(256) void split_h_k(
    const float4* __restrict__ in, __half2* __restrict__ hi,
    __half2* __restrict__ lo, long long n4)
{
    long long i = (long long)blockIdx.x * 256 + threadIdx.x;
    if (i >= n4) return;
    float4 v = in[i];
    __half h0,h1,h2,h3,l0,l1,l2,l3;
    split1h(v.x,h0,l0); split1h(v.y,h1,l1); split1h(v.z,h2,l2); split1h(v.w,h3,l3);
    hi[2*i]   = __halves2half2(h0,h1);
    hi[2*i+1] = __halves2half2(h2,h3);
    lo[2*i]   = __halves2half2(l0,l1);
    lo[2*i+1] = __halves2half2(l2,l3);
}

// convert w1 (interleave even rows), w3 (odd rows), w2 (straight), wo (straight)
__global__ __launch_bounds__(256) void conv4_h_k(
    const float4* __restrict__ w1, const float4* __restrict__ w3,
    const float4* __restrict__ w2, const float4* __restrict__ wo,
    __half2* __restrict__ w13, __half2* __restrict__ w2h, __half2* __restrict__ woh,
    long long n4big, long long n4wo)
{
    long long i = (long long)blockIdx.x * 256 + threadIdx.x;
    int which = blockIdx.y;
    if (which <= 1) {
        if (i >= n4big) return;
        const float4* s = which ? w3 : w1;
        float4 v = s[i];
        long long row = i / (CD/4), off = i % (CD/4);
        long long orow = 2*row + which;
        __half2* d = w13 + orow * (CD/2) + off*2;
        d[0] = __floats2half2_rn(v.x, v.y);
        d[1] = __floats2half2_rn(v.z, v.w);
    } else if (which == 2) {
        if (i >= n4big) return;
        float4 v = w2[i];
        w2h[2*i]   = __floats2half2_rn(v.x, v.y);
        w2h[2*i+1] = __floats2half2_rn(v.z, v.w);
    } else {
        if (i >= n4wo) return;
        float4 v = wo[i];
        woh[2*i]   = __floats2half2_rn(v.x, v.y);
        woh[2*i+1] = __floats2half2_rn(v.z, v.w);
    }
}

// ------------------------------ RMSNorm variants ----------------------------
__device__ __forceinline__ float rms_scale(const float* ip, int K, int tid) {
    float s = 0.f;
    for (int i = tid; i < K; i += 256) { float v = ip[i]; s += v * v; }
    __shared__ float red[32];
    #pragma unroll
    for (int o = 16; o > 0; o >>= 1) s += __shfl_xor_sync(0xffffffffu, s, o);
    int warp = tid >> 5, lane = tid & 31;
    if (lane == 0) red[warp] = s;
    __syncthreads();
    if (warp == 0) {
        float s2 = (lane < 8) ? red[lane] : 0.f;
        #pragma unroll
        for (int o = 4; o > 0; o >>= 1) s2 += __shfl_xor_sync(0xffffffffu, s2, o);
        if (lane == 0) red[0] = s2;
    }
    __syncthreads();
    return rsqrtf(red[0] / (float)K + 1e-6f);
}

__global__ __launch_bounds__(256) void rmsnorm_split_h_k(
    const float* __restrict__ in, int ldin, const float* __restrict__ w,
    __half* __restrict__ hi, __half* __restrict__ lo, int K)
{
    long long row = blockIdx.x;
    const float* ip = in + row * ldin;
    float scale = rms_scale(ip, K, threadIdx.x);
    for (int i = threadIdx.x; i < K; i += 256) {
        float v = ip[i] * scale * w[i];
        __half h, l; split1h(v, h, l);
        hi[row * (long long)K + i] = h;
        lo[row * (long long)K + i] = l;
    }
}

__global__ __launch_bounds__(256) void rmsnorm_h_k(
    const float* __restrict__ in, int ldin, const float* __restrict__ w,
    __half* __restrict__ out, int K)
{
    long long row = blockIdx.x;
    const float* ip = in + row * ldin;
    float scale = rms_scale(ip, K, threadIdx.x);
    for (int i = threadIdx.x; i < K; i += 256)
        out[row * (long long)K + i] = __float2half_rn(ip[i] * scale * w[i]);
}

// ------------------- RoPE + head packing (qf/kf pairs, vT single) -----------
__global__ __launch_bounds__(256) void rope_pack_h_k(
    const float* __restrict__ q, const float* __restrict__ kv,
    const float* __restrict__ qkva,
    const float* __restrict__ fcos, const float* __restrict__ fsin,
    __half* __restrict__ qfH, __half* __restrict__ qfL,
    __half* __restrict__ kfH, __half* __restrict__ kfL,
    __half* __restrict__ vT)
{
    int t = blockIdx.x, b = blockIdx.y;
    long long m = (long long)b * CT + t;
    __shared__ float kpe[CROPE], cs[32], sn[32];
    int tid = threadIdx.x;
    if (tid < 32) { cs[tid] = fcos[t*32 + tid]; sn[tid] = fsin[t*32 + tid]; }
    __syncthreads();
    if (tid < 32) {
        float x0 = qkva[m*NQKVA + 2048 + 2*tid];
        float x1 = qkva[m*NQKVA + 2048 + 2*tid + 1];
        kpe[2*tid]   = x0*cs[tid] - x1*sn[tid];
        kpe[2*tid+1] = x0*sn[tid] + x1*cs[tid];
    }
    __syncthreads();
    for (int idx = tid; idx < CH*CQKD; idx += 256) {
        int h = idx / CQKD, d = idx % CQKD;
        long long o = (((long long)b*CH + h)*CT + t)*CQKD + d;
        float qv, kvv;
        if (d < CNOPE) {
            qv  = q [m*(CH*CQKD) + h*CQKD + d];
            kvv = kv[m*(CH*256)  + h*256  + d];
        } else {
            int j = d - CNOPE, i2 = j >> 1;
            float x0 = q[m*(CH*CQKD) + h*CQKD + CNOPE + 2*i2];
            float x1 = q[m*(CH*CQKD) + h*CQKD + CNOPE + 2*i2 + 1];
            qv  = (j & 1) ? (x0*sn[i2] + x1*cs[i2]) : (x0*cs[i2] - x1*sn[i2]);
            kvv = kpe[j];
        }
        __half hh, ll;
        split1h(qv, hh, ll);  qfH[o] = hh; qfL[o] = ll;
        split1h(kvv, hh, ll); kfH[o] = hh; kfL[o] = ll;
    }
    for (int idx = tid; idx < CH*CVHD; idx += 256) {
        int h = idx >> 7, d = idx & 127;
        vT[(((long long)b*CH + h)*CVHD + d)*CT + t] =
            __float2half_rn(kv[m*(CH*256) + h*256 + CNOPE + d]);
    }
}

// ------------------- causal softmax (fp16 out, skip masked reads) -----------
__global__ __launch_bounds__(256) void softmax_causal_h_k(
    const float* __restrict__ s, __half* __restrict__ at)
{
    long long row = blockIdx.x;
    int sIdx = (int)(row & (CT - 1));
    const float4* p = (const float4*)(s + row * (long long)CT);
    int tid = threadIdx.x, warp = tid >> 5, lane = tid & 31;
    __shared__ float red[32];

    bool act = (4 * tid <= sIdx);
    float4 v = act ? p[tid] : make_float4(-1e30f, -1e30f, -1e30f, -1e30f);
    float mx = fmaxf(fmaxf(v.x, v.y), fmaxf(v.z, v.w));
    #pragma unroll
    for (int o = 16; o > 0; o >>= 1) mx = fmaxf(mx, __shfl_xor_sync(0xffffffffu, mx, o));
    if (lane == 0) red[warp] = mx;
    __syncthreads();
    if (warp == 0) {
        float m2 = (lane < 8) ? red[lane] : -1e30f;
        #pragma unroll
        for (int o = 4; o > 0; o >>= 1) m2 = fmaxf(m2, __shfl_xor_sync(0xffffffffu, m2, o));
        if (lane == 0) red[0] = m2;
    }
    __syncthreads();
    mx = red[0];
    __syncthreads();

    float sum = 0.f;
    if (act) {
        v.x = __expf(v.x - mx); v.y = __expf(v.y - mx);
        v.z = __expf(v.z - mx); v.w = __expf(v.w - mx);
        sum = v.x + v.y + v.z + v.w;
    }
    #pragma unroll
    for (int o = 16; o > 0; o >>= 1) sum += __shfl_xor_sync(0xffffffffu, sum, o);
    if (lane == 0) red[warp] = sum;
    __syncthreads();
    if (warp == 0) {
        float s2 = (lane < 8) ? red[lane] : 0.f;
        #pragma unroll
        for (int o = 4; o > 0; o >>= 1) s2 += __shfl_xor_sync(0xffffffffu, s2, o);
        if (lane == 0) red[0] = s2;
    }
    __syncthreads();
    float inv = 1.f / red[0];
    __half2* H = (__half2*)(at + row * (long long)CT);
    if (act) {
        H[2*tid]   = __floats2half2_rn(v.x * inv, v.y * inv);
        H[2*tid+1] = __floats2half2_rn(v.z * inv, v.w * inv);
    } else {
        H[2*tid]   = __halves2half2(__float2half_rn(0.f), __float2half_rn(0.f));
        H[2*tid+1] = H[2*tid];
    }
}

// ================ templated fp16 HMMA GEMM (512 thr, 256x128 tile) ==========
// TERMS=3: C = alpha*(Ah@Bh + Ah@Bl + Al@Bh) [+R];  TERMS=1: C = alpha*Ah@Bh [+R]
// HOUT: 0=float(+R), 1=half, 2=gu-fused (silu(even col)*odd col -> half)
// C offset per z: (z/zdiv)*sC + (z%zdiv)*sC2
// causal: 1 = skip when bn > bm+255;  2 = truncate K at bm+256.
// M % 256 == 0 required.
template<int TERMS>
__device__ __forceinline__ void issue_h(
    uint32_t sbase, const __half* Ah, const __half* Al,
    const __half* Bh, const __half* Bl,
    int lda, int ldb, int bm, int bn, int N, int k0, int tid)
{
    constexpr int OPS = (TERMS == 3) ? 2 : 1;
    constexpr int ABYTES = 32768 * OPS;
    // A: 256 rows x 128B
    #pragma unroll
    for (int it = 0; it < 4; it++) {
        int e = it * 512 + tid;
        int r = e >> 3, g = e & 7;
        uint32_t so = SW128(r * 128 + g * 16);
        cpa16(sbase + so, Ah + (size_t)(bm + r) * lda + k0 + g * 8, 16);
        if constexpr (TERMS == 3)
            cpa16(sbase + 32768 + so, Al + (size_t)(bm + r) * lda + k0 + g * 8, 16);
    }
    // B: 128 rows x 128B
    #pragma unroll
    for (int it = 0; it < 2; it++) {
        int e = it * 512 + tid;
        int r = e >> 3, g = e & 7;
        uint32_t so = SW128(r * 128 + g * 16);
        int rb = bn + r; int pb = (rb < N) ? 16 : 0; if (!pb) rb = 0;
        cpa16(sbase + ABYTES + so, Bh + (size_t)rb * ldb + k0 + g * 8, pb);
        if constexpr (TERMS == 3)
            cpa16(sbase + ABYTES + 16384 + so, Bl + (size_t)rb * ldb + k0 + g * 8, pb);
    }
    cp_commit();
}

template<int TERMS, int HOUT>
__global__ __launch_bounds__(512, 1) void gemm_h(
    const __half* __restrict__ Ah, const __half* __restrict__ Al,
    int lda, long long sA,
    const __half* __restrict__ Bh, const __half* __restrict__ Bl,
    int ldb, long long sB,
    void* __restrict__ Cv, int ldc, long long sC, int zdiv, long long sC2,
    const float* __restrict__ R, int ldr, long long sR,
    int M, int N, int K, float alpha, int causal)
{
    constexpr int OPS = (TERMS == 3) ? 2 : 1;
    constexpr int ABYTES = 32768 * OPS;                 // A hi(+lo)
    constexpr int STAGE  = ABYTES + 16384 * OPS;        // + B hi(+lo)
    constexpr int NST    = (TERMS == 1) ? 4 : 2;

    extern __shared__ __align__(1024) char smem[];
    const uint32_t sb0 = smem_u32(smem);
    const int tid = threadIdx.x;
    const int wid = tid >> 5, lane = tid & 31;
    long long z = blockIdx.z;
    Ah += z * sA;
    if constexpr (TERMS == 3) Al += z * sA;
    Bh += z * sB;
    if constexpr (TERMS == 3) Bl += z * sB;
    if (R) R += z * sR;
    const long long zo = (z / zdiv) * sC + (z % zdiv) * sC2;
    const int bm = blockIdx.y * 256, bn = blockIdx.x * 128;
    // 16 warps: 4 (M) x 4 (N); warp tile 64 x 32
    const int wm = (wid >> 2) * 64, wn = (wid & 3) * 32;

    if (causal == 1 && bn > bm + 255) return;

    float acc[4][4][4];
    #pragma unroll
    for (int i = 0; i < 4; i++)
        #pragma unroll
        for (int j = 0; j < 4; j++)
            #pragma unroll
            for (int r = 0; r < 4; r++) acc[i][j][r] = 0.f;

    int nc = K >> 6;
    if (causal == 2) { int lim = (bm + 319) >> 6; if (lim < nc) nc = lim; }

    #pragma unroll
    for (int s = 0; s < NST - 1; s++) {
        if (s < nc)
            issue_h<TERMS>(sb0 + s * STAGE, Ah, Al, Bh, Bl, lda, ldb, bm, bn, N, s << 6, tid);
        else
            cp_commit();
    }

    const int arow = wm + (lane & 15);
    const int acb  = (lane >> 4) << 4;
    const int brow4 = wn + ((lane >> 4) << 3) + (lane & 7);
    const int bcb4  = ((lane >> 3) & 1) << 4;

    uint32_t bhf[2][4], blf[2][4];
    (void)blf;

    for (int c = 0; c < nc; c++) {
        cp_wait<NST - 2>();
        __syncthreads();
        {
            int nx = c + NST - 1;
            if (nx < nc)
                issue_h<TERMS>(sb0 + (nx % NST) * STAGE, Ah, Al, Bh, Bl,
                               lda, ldb, bm, bn, N, nx << 6, tid);
            else
                cp_commit();
        }

        uint32_t tA  = sb0 + (c % NST) * STAGE;
        uint32_t tAl = tA + 32768;
        uint32_t tB  = tA + ABYTES;
        uint32_t tBl = tB + 16384;

        #pragma unroll
        for (int ks = 0; ks < 4; ks++) {
            // B fragments batched (reused across 4 ms steps)
            #pragma unroll
            for (int ng4 = 0; ng4 < 2; ng4++) {
                uint32_t off = SW128((brow4 + ng4 * 16) * 128 + ks * 32 + bcb4);
                ldsm_x4(bhf[ng4], tB + off);
                if constexpr (TERMS == 3) ldsm_x4(blf[ng4], tBl + off);
            }
            // A fragments streamed per 16-row step
            #pragma unroll
            for (int ms = 0; ms < 4; ms++) {
                uint32_t ahf[4], alf[4];
                uint32_t off = SW128((arow + ms * 16) * 128 + ks * 32 + acb);
                ldsm_x4(ahf, tA + off);
                if constexpr (TERMS == 3) ldsm_x4(alf, tAl + off);
                #pragma unroll
                for (int ng4 = 0; ng4 < 2; ng4++) {
                    mma_f16(acc[ms][2*ng4],   ahf, bhf[ng4]);
                    mma_f16(acc[ms][2*ng4+1], ahf, bhf[ng4] + 2);
                    if constexpr (TERMS == 3) {
                        mma_f16(acc[ms][2*ng4],   ahf, blf[ng4]);
                        mma_f16(acc[ms][2*ng4+1], ahf, blf[ng4] + 2);
                        mma_f16(acc[ms][2*ng4],   alf, bhf[ng4]);
                        mma_f16(acc[ms][2*ng4+1], alf, bhf[ng4] + 2);
                    }
                }
            }
        }
    }

    const int gid = lane >> 2, tc = lane & 3;
    if constexpr (HOUT == 2) {
        __half* C = (__half*)Cv + zo;
        #pragma unroll
        for (int ms = 0; ms < 4; ms++)
            #pragma unroll
            for (int ns = 0; ns < 4; ns++) {
                int gr0 = bm + wm + ms * 16 + gid;
                int gc  = bn + wn + ns * 8 + tc * 2;
                float g0 = acc[ms][ns][0], u0 = acc[ms][ns][1];
                float g1 = acc[ms][ns][2], u1 = acc[ms][ns][3];
                float r0 = g0 / (1.f + __expf(-g0)) * u0;
                float r1 = g1 / (1.f + __expf(-g1)) * u1;
                C[(size_t)gr0 * ldc + (gc >> 1)]       = __float2half_rn(r0);
                C[(size_t)(gr0 + 8) * ldc + (gc >> 1)] = __float2half_rn(r1);
            }
    } else if constexpr (HOUT == 1) {
        __half* C = (__half*)Cv + zo;
        #pragma unroll
        for (int ms = 0; ms < 4; ms++)
            #pragma unroll
            for (int ns = 0; ns < 4; ns++) {
                int gr0 = bm + wm + ms * 16 + gid;
                int gc  = bn + wn + ns * 8 + tc * 2;
                if (gc < N) {
                    *(__half2*)&C[(size_t)gr0 * ldc + gc] =
                        __floats2half2_rn(alpha * acc[ms][ns][0], alpha * acc[ms][ns][1]);
                    *(__half2*)&C[(size_t)(gr0 + 8) * ldc + gc] =
                        __floats2half2_rn(alpha * acc[ms][ns][2], alpha * acc[ms][ns][3]);
                }
            }
    } else {
        float* C = (float*)Cv + zo;
        #pragma unroll
        for (int ms = 0; ms < 4; ms++)
            #pragma unroll
            for (int ns = 0; ns < 4; ns++) {
                int gr0 = bm + wm + ms * 16 + gid;
                int gc  = bn + wn + ns * 8 + tc * 2;
                if (gc < N) {
                    float2 v0;
                    v0.x = alpha * acc[ms][ns][0];
                    v0.y = alpha * acc[ms][ns][1];
                    if (R) { v0.x += R[(size_t)gr0 * ldr + gc]; v0.y += R[(size_t)gr0 * ldr + gc + 1]; }
                    *(float2*)&C[(size_t)gr0 * ldc + gc] = v0;
                    int gr1 = gr0 + 8;
                    float2 v1;
                    v1.x = alpha * acc[ms][ns][2];
                    v1.y = alpha * acc[ms][ns][3];
                    if (R) { v1.x += R[(size_t)gr1 * ldr + gc]; v1.y += R[(size_t)gr1 * ldr + gc + 1]; }
                    *(float2*)&C[(size_t)gr1 * ldc + gc] = v1;
                }
            }
    }
}

#define SM_3 (2*(65536+32768))   // 196608
#define SM_1 (4*(32768+16384))   // 196608

// ------------------------------ host launch ---------------------------------
static void gemm3(const __half* Ah, const __half* Al, int lda, long long sA,
                  const __half* Bh, const __half* Bl, int ldb, long long sB,
                  float* C, int ldc, long long sC,
                  const float* R, int ldr, long long sR,
                  int M, int N, int K, float alpha, int Z, int causal = 0)
{
    dim3 grid((N + 127) / 128, M / 256, Z);
    gemm_h<3,0><<<grid, 512, SM_3>>>(Ah, Al, lda, sA, Bh, Bl, ldb, sB,
                                     C, ldc, sC, 1, 0, R, ldr, sR, M, N, K, alpha, causal);
}
static void gemm1f(const __half* A, int lda, long long sA,
                   const __half* B, int ldb, long long sB,
                   float* C, int ldc, long long sC,
                   const float* R, int ldr, long long sR,
                   int M, int N, int K, float alpha, int Z, int causal = 0)
{
    dim3 grid((N + 127) / 128, M / 256, Z);
    gemm_h<1,0><<<grid, 512, SM_1>>>(A, nullptr, lda, sA, B, nullptr, ldb, sB,
                                     C, ldc, sC, 1, 0, R, ldr, sR, M, N, K, alpha, causal);
}

static void splitp_s(cudaStream_t st, const float* in, __half* hi, __half* lo, long long n)
{
    long long n4 = n >> 2;
    split_h_k<<<(unsigned)((n4 + 255) / 256), 256, 0, st>>>(
        (const float4*)in, (__half2*)hi, (__half2*)lo, n4);
}

extern "C" void kernel_launch(void* const* d_in, const int* in_sizes, int n_in,
                              void* d_out, int out_size)
{
    const float* x     = (const float*)d_in[0];
    const float* mask  = (const float*)d_in[1];
    const float* fcos  = (const float*)d_in[2];
    const float* fsin  = (const float*)d_in[3];
    const float* anw   = (const float*)d_in[4];
    const float* wq_a  = (const float*)d_in[5];
    const float* qnw   = (const float*)d_in[6];
    const float* wq_b  = (const float*)d_in[7];
    const float* wkv_a = (const float*)d_in[8];
    const float* kvnw  = (const float*)d_in[9];
    const float* wkv_b = (const float*)d_in[10];
    const float* wo    = (const float*)d_in[11];
    const float* fnw   = (const float*)d_in[12];
    const float* w1    = (const float*)d_in[13];
    const float* w2    = (const float*)d_in[14];
    const float* w3    = (const float*)d_in[15];
    float* out = (float*)d_out;

    cudaFuncSetAttribute(gemm_h<3,0>, cudaFuncAttributeMaxDynamicSharedMemorySize, SM_3);
    cudaFuncSetAttribute(gemm_h<1,0>, cudaFuncAttributeMaxDynamicSharedMemorySize, SM_1);
    cudaFuncSetAttribute(gemm_h<1,1>, cudaFuncAttributeMaxDynamicSharedMemorySize, SM_1);
    cudaFuncSetAttribute(gemm_h<1,2>, cudaFuncAttributeMaxDynamicSharedMemorySize, SM_1);

    float *p_qkva, *p_q, *p_kv, *p_sc, *p_x2;
    cudaGetSymbolAddress((void**)&p_qkva, g_qkva);
    cudaGetSymbolAddress((void**)&p_q,    g_q);
    cudaGetSymbolAddress((void**)&p_kv,   g_kv);
    cudaGetSymbolAddress((void**)&p_sc,   g_sc);
    cudaGetSymbolAddress((void**)&p_x2,   g_x2);

    __half *hH,*hL,*qaH,*qaL,*kvnH,*kvnL,*qfH,*qfL,*kfH,*kfL,*vT,*at,*y2,*h2,*gs,
           *wqkaH,*wqkaL,*wqbH,*wqbL,*wkbH,*wkbL,*woh,*w13h,*w2h;
    cudaGetSymbolAddress((void**)&hH,   f_hH);  cudaGetSymbolAddress((void**)&hL,   f_hL);
    cudaGetSymbolAddress((void**)&qaH,  f_qaH); cudaGetSymbolAddress((void**)&qaL,  f_qaL);
    cudaGetSymbolAddress((void**)&kvnH, f_kvnH);cudaGetSymbolAddress((void**)&kvnL, f_kvnL);
    cudaGetSymbolAddress((void**)&qfH,  f_qfH); cudaGetSymbolAddress((void**)&qfL,  f_qfL);
    cudaGetSymbolAddress((void**)&kfH,  f_kfH); cudaGetSymbolAddress((void**)&kfL,  f_kfL);
    cudaGetSymbolAddress((void**)&vT,   f_vT);  cudaGetSymbolAddress((void**)&at,   f_at);
    cudaGetSymbolAddress((void**)&y2,   f_y2);
    cudaGetSymbolAddress((void**)&h2,   f_h2);  cudaGetSymbolAddress((void**)&gs,   f_gs);
    cudaGetSymbolAddress((void**)&wqkaH,f_wqkaH);cudaGetSymbolAddress((void**)&wqkaL,f_wqkaL);
    cudaGetSymbolAddress((void**)&wqbH, f_wqbH);cudaGetSymbolAddress((void**)&wqbL, f_wqbL);
    cudaGetSymbolAddress((void**)&wkbH, f_wkbH);cudaGetSymbolAddress((void**)&wkbL, f_wkbL);
    cudaGetSymbolAddress((void**)&woh,  f_wo);
    cudaGetSymbolAddress((void**)&w13h, f_w13); cudaGetSymbolAddress((void**)&w2h,  f_w2);

    // ---- forked stream for weight conversions (capture-legal fork/join) ----
    cudaStream_t s1;
    cudaStreamCreateWithFlags(&s1, cudaStreamNonBlocking);
    cudaEvent_t evFork, evQKA, evQB, evKB, evConv;
    cudaEventCreateWithFlags(&evFork, cudaEventDisableTiming);
    cudaEventCreateWithFlags(&evQKA,  cudaEventDisableTiming);
    cudaEventCreateWithFlags(&evQB,   cudaEventDisableTiming);
    cudaEventCreateWithFlags(&evKB,   cudaEventDisableTiming);
    cudaEventCreateWithFlags(&evConv, cudaEventDisableTiming);

    cudaEventRecord(evFork, 0);
    cudaStreamWaitEvent(s1, evFork, 0);

    // s1: all weight conversions, ordered by when main needs them
    splitp_s(s1, wq_a,  wqkaH, wqkaL, (long long)CQLORA*CD);
    splitp_s(s1, wkv_a, wqkaH + (long long)CQLORA*CD, wqkaL + (long long)CQLORA*CD,
             (long long)(CKVLORA+CROPE)*CD);
    cudaEventRecord(evQKA, s1);
    splitp_s(s1, wq_b, wqbH, wqbL, (long long)CH*CQKD*CQLORA);
    cudaEventRecord(evQB, s1);
    splitp_s(s1, wkv_b, wkbH, wkbL, (long long)CH*256*CKVLORA);
    cudaEventRecord(evKB, s1);
    {
        long long n4big = ((long long)CINTER * CD) >> 2;
        long long n4wo  = ((long long)CD * CD) >> 2;
        dim3 grid((unsigned)((n4big + 255) / 256), 4);
        conv4_h_k<<<grid, 256, 0, s1>>>((const float4*)w1, (const float4*)w3,
                                        (const float4*)w2, (const float4*)wo,
                                        (__half2*)w13h, (__half2*)w2h, (__half2*)woh,
                                        n4big, n4wo);
    }
    cudaEventRecord(evConv, s1);

    // ---- main stream: attention path ----
    rmsnorm_split_h_k<<<CM, 256>>>(x, CD, anw, hH, hL, CD);
    cudaStreamWaitEvent(0, evQKA, 0);
    // qkva = h @ [wq_a; wkv_a]^T
    gemm3(hH, hL, CD, 0, wqkaH, wqkaL, CD, 0, p_qkva, NQKVA, 0,
          nullptr, 0, 0, CM, NQKVA, CD, 1.f, 1);
    rmsnorm_split_h_k<<<CM, 256>>>(p_qkva, NQKVA, qnw, qaH, qaL, CQLORA);
    cudaStreamWaitEvent(0, evQB, 0);
    // q = qa_norm @ wq_b^T
    gemm3(qaH, qaL, CQLORA, 0, wqbH, wqbL, CQLORA, 0, p_q, CH*CQKD, 0,
          nullptr, 0, 0, CM, CH*CQKD, CQLORA, 1.f, 1);
    rmsnorm_split_h_k<<<CM, 256>>>(p_qkva + CQLORA, NQKVA, kvnw, kvnH, kvnL, CKVLORA);
    cudaStreamWaitEvent(0, evKB, 0);
    // kv = kv_norm @ wkv_b^T
    gemm3(kvnH, kvnL, CKVLORA, 0, wkbH, wkbL, CKVLORA, 0, p_kv, CH*256, 0,
          nullptr, 0, 0, CM, CH*256, CKVLORA, 1.f, 1);
    rope_pack_h_k<<<dim3(CT, CB), 256>>>(p_q, p_kv, p_qkva, fcos, fsin,
                                         qfH, qfL, kfH, kfL, vT);
    // scores = -96 * qf @ kf^T + mask (masked tiles skipped; softmax fills zeros)
    gemm3(qfH, qfL, CQKD, (long long)CT*CQKD,
          kfH, kfL, CQKD, (long long)CT*CQKD,
          p_sc, CT, (long long)CT*CT,
          mask, CT, 0, CT, CT, CQKD, -96.f, CB*CH, 1);
    softmax_causal_h_k<<<CB*CH*CT, 256>>>(p_sc, at);
    // y2 = attn @ vT with fused [B,H,T,d] -> [B*T, H*d] permute in epilogue
    {
        dim3 grid(1, CT / 256, CB*CH);
        gemm_h<1,1><<<grid, 512, SM_1>>>(
            at, nullptr, CT, (long long)CT*CT,
            vT, nullptr, CT, (long long)CVHD*CT,
            y2, CD, (long long)CT*CD, CH, (long long)CVHD,
            nullptr, 0, 0, CT, CVHD, CT, 1.f, 2);
    }
    // join conversion stream before first consumer of woh/w13h/w2h
    cudaStreamWaitEvent(0, evConv, 0);
    // x2 = x + y2 @ wo^T
    gemm1f(y2, CH*CVHD, 0, woh, CH*CVHD, 0, p_x2, CD, 0,
           x, CD, 0, CM, CD, CH*CVHD, 1.f, 1);

    // ---- FFN path ----
    rmsnorm_h_k<<<CM, 256>>>(p_x2, CD, fnw, h2, CD);
    // gs = silu(h2@w1^T) * (h2@w3^T) in ONE GEMM (w13 interleaved, fused epilogue)
    {
        dim3 grid((2*CINTER) / 128, CM / 256, 1);
        gemm_h<1,2><<<grid, 512, SM_1>>>(
            h2, nullptr, CD, 0,
            w13h, nullptr, CD, 0,
            gs, CINTER, 0, 1, 0,
            nullptr, 0, 0, CM, 2*CINTER, CD, 1.f, 0);
    }
    // out = x2 + gs @ w2^T
    gemm1f(gs, CINTER, 0, w2h, CINTER, 0, out, CD, 0,
           p_x2, CD, 0, CM, CD, CINTER, 1.f, 1);
}

// round 14
// speedup vs baseline: 1.0624x; 1.0624x over previous
#include <cuda_runtime.h>
#include <cuda_fp16.h>
#include <cstdint>

// ---------------------------------------------------------------------------
// DeepSeek MLA block on GB300 — mma.sync fp16 GEMMs, v12.
// q/k path: fp16-pair 3-term split. Additive paths: 1-term fp16.
// v12 = v11 (parallel q/kv streams + conversion stream) with streams/events
//       created ONCE on first call (static cache) so no allocation occurs
//       after the harness's pre-capture memory baseline.
// ---------------------------------------------------------------------------

#define CB 2
#define CT 1024
#define CD 2048
#define CH 16
#define CNOPE 128
#define CROPE 64
#define CQKD 192
#define CQLORA 1536
#define CKVLORA 512
#define CVHD 128
#define CINTER 8192
#define CM (CB*CT)
#define NQKVA (CQLORA + CKVLORA + CROPE)   // 2112

// ------------------------------- PTX helpers -------------------------------
__device__ __forceinline__ uint32_t smem_u32(const void* p) {
    uint32_t a;
    asm("{ .reg .u64 t; cvta.to.shared.u64 t, %1; cvt.u32.u64 %0, t; }" : "=r"(a) : "l"(p));
    return a;
}
#define SW128(o) ((o) ^ (((o) >> 3) & 0x70))

__device__ __forceinline__ void cpa16(uint32_t s, const void* g, int sz) {
    asm volatile("cp.async.cg.shared.global [%0], [%1], 16, %2;"
                 :: "r"(s), "l"(g), "r"(sz));
}
__device__ __forceinline__ void cp_commit() {
    asm volatile("cp.async.commit_group;" ::: "memory");
}
template <int N> __device__ __forceinline__ void cp_wait() {
    asm volatile("cp.async.wait_group %0;" :: "n"(N) : "memory");
}
__device__ __forceinline__ void ldsm_x4(uint32_t* r, uint32_t a) {
    asm volatile("ldmatrix.sync.aligned.m8n8.x4.shared.b16 {%0,%1,%2,%3}, [%4];"
        : "=r"(r[0]), "=r"(r[1]), "=r"(r[2]), "=r"(r[3]) : "r"(a));
}
__device__ __forceinline__ void mma_f16(float* d, const uint32_t* a, const uint32_t* b) {
    asm volatile(
        "mma.sync.aligned.m16n8k16.row.col.f32.f16.f16.f32 "
        "{%0,%1,%2,%3}, {%4,%5,%6,%7}, {%8,%9}, {%0,%1,%2,%3};"
        : "+f"(d[0]), "+f"(d[1]), "+f"(d[2]), "+f"(d[3])
        : "r"(a[0]), "r"(a[1]), "r"(a[2]), "r"(a[3]), "r"(b[0]), "r"(b[1]));
}

// ------------------------- scratch (device globals) ------------------------
__device__ float g_qkva[(long long)CM*NQKVA];
__device__ float g_q   [(long long)CM*CH*CQKD];
__device__ float g_kv  [(long long)CM*CH*(CNOPE+CVHD)];
__device__ float g_sc  [(long long)CB*CH*CT*CT];
__device__ float g_x2  [(long long)CM*CD];

// fp16 operand buffers
__device__ __half f_hH [(long long)CM*CD],        f_hL [(long long)CM*CD];
__device__ __half f_qaH[(long long)CM*CQLORA],    f_qaL[(long long)CM*CQLORA];
__device__ __half f_kvnH[(long long)CM*CKVLORA],  f_kvnL[(long long)CM*CKVLORA];
__device__ __half f_qfH[(long long)CB*CH*CT*CQKD], f_qfL[(long long)CB*CH*CT*CQKD];
__device__ __half f_kfH[(long long)CB*CH*CT*CQKD], f_kfL[(long long)CB*CH*CT*CQKD];
__device__ __half f_vT [(long long)CB*CH*CVHD*CT];
__device__ __half f_at [(long long)CB*CH*CT*CT];
__device__ __half f_y2 [(long long)CM*CD];
__device__ __half f_h2 [(long long)CM*CD];
__device__ __half f_gs [(long long)CM*CINTER];
// weights
__device__ __half f_wqkaH[(long long)NQKVA*CD],   f_wqkaL[(long long)NQKVA*CD];
__device__ __half f_wqbH[(long long)CH*CQKD*CQLORA], f_wqbL[(long long)CH*CQKD*CQLORA];
__device__ __half f_wkbH[(long long)CH*256*CKVLORA], f_wkbL[(long long)CH*256*CKVLORA];
__device__ __half f_wo [(long long)CD*CD];
__device__ __half f_w13[(long long)2*CINTER*CD];   // interleaved: row 2j=w1_j, 2j+1=w3_j
__device__ __half f_w2 [(long long)CD*CINTER];

// ------------------------------- split helpers -----------------------------
__device__ __forceinline__ void split1h(float v, __half& h, __half& l) {
    h = __float2half_rn(v);
    l = __float2half_rn(v - __half2float(h));
}

__global__ __launch_bounds__(256) void split_h_k(
    const float4* __restrict__ in, __half2* __restrict__ hi,
    __half2* __restrict__ lo, long long n4)
{
    long long i = (long long)blockIdx.x * 256 + threadIdx.x;
    if (i >= n4) return;
    float4 v = in[i];
    __half h0,h1,h2,h3,l0,l1,l2,l3;
    split1h(v.x,h0,l0); split1h(v.y,h1,l1); split1h(v.z,h2,l2); split1h(v.w,h3,l3);
    hi[2*i]   = __halves2half2(h0,h1);
    hi[2*i+1] = __halves2half2(h2,h3);
    lo[2*i]   = __halves2half2(l0,l1);
    lo[2*i+1] = __halves2half2(l2,l3);
}

// convert w1 (interleave even rows), w3 (odd rows), w2 (straight), wo (straight)
__global__ __launch_bounds__(256) void conv4_h_k(
    const float4* __restrict__ w1, const float4* __restrict__ w3,
    const float4* __restrict__ w2, const float4* __restrict__ wo,
    __half2* __restrict__ w13, __half2* __restrict__ w2h, __half2* __restrict__ woh,
    long long n4big, long long n4wo)
{
    long long i = (long long)blockIdx.x * 256 + threadIdx.x;
    int which = blockIdx.y;
    if (which <= 1) {
        if (i >= n4big) return;
        const float4* s = which ? w3 : w1;
        float4 v = s[i];
        long long row = i / (CD/4), off = i % (CD/4);
        long long orow = 2*row + which;
        __half2* d = w13 + orow * (CD/2) + off*2;
        d[0] = __floats2half2_rn(v.x, v.y);
        d[1] = __floats2half2_rn(v.z, v.w);
    } else if (which == 2) {
        if (i >= n4big) return;
        float4 v = w2[i];
        w2h[2*i]   = __floats2half2_rn(v.x, v.y);
        w2h[2*i+1] = __floats2half2_rn(v.z, v.w);
    } else {
        if (i >= n4wo) return;
        float4 v = wo[i];
        woh[2*i]   = __floats2half2_rn(v.x, v.y);
        woh[2*i+1] = __floats2half2_rn(v.z, v.w);
    }
}

// ------------------------------ RMSNorm variants ----------------------------
__device__ __forceinline__ float rms_scale(const float* ip, int K, int tid) {
    float s = 0.f;
    for (int i = tid; i < K; i += 256) { float v = ip[i]; s += v * v; }
    __shared__ float red[32];
    #pragma unroll
    for (int o = 16; o > 0; o >>= 1) s += __shfl_xor_sync(0xffffffffu, s, o);
    int warp = tid >> 5, lane = tid & 31;
    if (lane == 0) red[warp] = s;
    __syncthreads();
    if (warp == 0) {
        float s2 = (lane < 8) ? red[lane] : 0.f;
        #pragma unroll
        for (int o = 4; o > 0; o >>= 1) s2 += __shfl_xor_sync(0xffffffffu, s2, o);
        if (lane == 0) red[0] = s2;
    }
    __syncthreads();
    return rsqrtf(red[0] / (float)K + 1e-6f);
}

__global__ __launch_bounds__(256) void rmsnorm_split_h_k(
    const float* __restrict__ in, int ldin, const float* __restrict__ w,
    __half* __restrict__ hi, __half* __restrict__ lo, int K)
{
    long long row = blockIdx.x;
    const float* ip = in + row * ldin;
    float scale = rms_scale(ip, K, threadIdx.x);
    for (int i = threadIdx.x; i < K; i += 256) {
        float v = ip[i] * scale * w[i];
        __half h, l; split1h(v, h, l);
        hi[row * (long long)K + i] = h;
        lo[row * (long long)K + i] = l;
    }
}

__global__ __launch_bounds__(256) void rmsnorm_h_k(
    const float* __restrict__ in, int ldin, const float* __restrict__ w,
    __half* __restrict__ out, int K)
{
    long long row = blockIdx.x;
    const float* ip = in + row * ldin;
    float scale = rms_scale(ip, K, threadIdx.x);
    for (int i = threadIdx.x; i < K; i += 256)
        out[row * (long long)K + i] = __float2half_rn(ip[i] * scale * w[i]);
}

// ------------------- RoPE + head packing (qf/kf pairs, vT single) -----------
__global__ __launch_bounds__(256) void rope_pack_h_k(
    const float* __restrict__ q, const float* __restrict__ kv,
    const float* __restrict__ qkva,
    const float* __restrict__ fcos, const float* __restrict__ fsin,
    __half* __restrict__ qfH, __half* __restrict__ qfL,
    __half* __restrict__ kfH, __half* __restrict__ kfL,
    __half* __restrict__ vT)
{
    int t = blockIdx.x, b = blockIdx.y;
    long long m = (long long)b * CT + t;
    __shared__ float kpe[CROPE], cs[32], sn[32];
    int tid = threadIdx.x;
    if (tid < 32) { cs[tid] = fcos[t*32 + tid]; sn[tid] = fsin[t*32 + tid]; }
    __syncthreads();
    if (tid < 32) {
        float x0 = qkva[m*NQKVA + 2048 + 2*tid];
        float x1 = qkva[m*NQKVA + 2048 + 2*tid + 1];
        kpe[2*tid]   = x0*cs[tid] - x1*sn[tid];
        kpe[2*tid+1] = x0*sn[tid] + x1*cs[tid];
    }
    __syncthreads();
    for (int idx = tid; idx < CH*CQKD; idx += 256) {
        int h = idx / CQKD, d = idx % CQKD;
        long long o = (((long long)b*CH + h)*CT + t)*CQKD + d;
        float qv, kvv;
        if (d < CNOPE) {
            qv  = q [m*(CH*CQKD) + h*CQKD + d];
            kvv = kv[m*(CH*256)  + h*256  + d];
        } else {
            int j = d - CNOPE, i2 = j >> 1;
            float x0 = q[m*(CH*CQKD) + h*CQKD + CNOPE + 2*i2];
            float x1 = q[m*(CH*CQKD) + h*CQKD + CNOPE + 2*i2 + 1];
            qv  = (j & 1) ? (x0*sn[i2] + x1*cs[i2]) : (x0*cs[i2] - x1*sn[i2]);
            kvv = kpe[j];
        }
        __half hh, ll;
        split1h(qv, hh, ll);  qfH[o] = hh; qfL[o] = ll;
        split1h(kvv, hh, ll); kfH[o] = hh; kfL[o] = ll;
    }
    for (int idx = tid; idx < CH*CVHD; idx += 256) {
        int h = idx >> 7, d = idx & 127;
        vT[(((long long)b*CH + h)*CVHD + d)*CT + t] =
            __float2half_rn(kv[m*(CH*256) + h*256 + CNOPE + d]);
    }
}

// ------------------- causal softmax (fp16 out, skip masked reads) -----------
__global__ __launch_bounds__(256) void softmax_causal_h_k(
    const float* __restrict__ s, __half* __restrict__ at)
{
    long long row = blockIdx.x;
    int sIdx = (int)(row & (CT - 1));
    const float4* p = (const float4*)(s + row * (long long)CT);
    int tid = threadIdx.x, warp = tid >> 5, lane = tid & 31;
    __shared__ float red[32];

    bool act = (4 * tid <= sIdx);
    float4 v = act ? p[tid] : make_float4(-1e30f, -1e30f, -1e30f, -1e30f);
    float mx = fmaxf(fmaxf(v.x, v.y), fmaxf(v.z, v.w));
    #pragma unroll
    for (int o = 16; o > 0; o >>= 1) mx = fmaxf(mx, __shfl_xor_sync(0xffffffffu, mx, o));
    if (lane == 0) red[warp] = mx;
    __syncthreads();
    if (warp == 0) {
        float m2 = (lane < 8) ? red[lane] : -1e30f;
        #pragma unroll
        for (int o = 4; o > 0; o >>= 1) m2 = fmaxf(m2, __shfl_xor_sync(0xffffffffu, m2, o));
        if (lane == 0) red[0] = m2;
    }
    __syncthreads();
    mx = red[0];
    __syncthreads();

    float sum = 0.f;
    if (act) {
        v.x = __expf(v.x - mx); v.y = __expf(v.y - mx);
        v.z = __expf(v.z - mx); v.w = __expf(v.w - mx);
        sum = v.x + v.y + v.z + v.w;
    }
    #pragma unroll
    for (int o = 16; o > 0; o >>= 1) sum += __shfl_xor_sync(0xffffffffu, sum, o);
    if (lane == 0) red[warp] = sum;
    __syncthreads();
    if (warp == 0) {
        float s2 = (lane < 8) ? red[lane] : 0.f;
        #pragma unroll
        for (int o = 4; o > 0; o >>= 1) s2 += __shfl_xor_sync(0xffffffffu, s2, o);
        if (lane == 0) red[0] = s2;
    }
    __syncthreads();
    float inv = 1.f / red[0];
    __half2* H = (__half2*)(at + row * (long long)CT);
    if (act) {
        H[2*tid]   = __floats2half2_rn(v.x * inv, v.y * inv);
        H[2*tid+1] = __floats2half2_rn(v.z * inv, v.w * inv);
    } else {
        H[2*tid]   = __halves2half2(__float2half_rn(0.f), __float2half_rn(0.f));
        H[2*tid+1] = H[2*tid];
    }
}

// ======================= templated fp16 HMMA GEMM (512 thr) =================
template<int TERMS, int BN>
__device__ __forceinline__ void issue_h(
    uint32_t sbase, const __half* Ah, const __half* Al,
    const __half* Bh, const __half* Bl,
    int lda, int ldb, int bm, int bn, int M, int N, int k0, int tid)
{
    constexpr int OPS = (TERMS == 3) ? 2 : 1;
    constexpr int ABYTES = 16384 * OPS;
    constexpr int NBT = BN / 128;
    #pragma unroll
    for (int it = 0; it < 2; it++) {
        int e = it * 512 + tid;
        int r = e >> 3, g = e & 7;
        uint32_t so = SW128(r * 128 + g * 16);
        int ra = bm + r; int pa = (ra < M) ? 16 : 0; if (!pa) ra = 0;
        cpa16(sbase + so, Ah + (size_t)ra * lda + k0 + g * 8, pa);
        if constexpr (TERMS == 3)
            cpa16(sbase + 16384 + so, Al + (size_t)ra * lda + k0 + g * 8, pa);
    }
    #pragma unroll
    for (int it = 0; it < 2 * NBT; it++) {
        int e = it * 512 + tid;
        int r = e >> 3, g = e & 7;
        uint32_t so = SW128(r * 128 + g * 16);
        int rb = bn + r; int pb = (rb < N) ? 16 : 0; if (!pb) rb = 0;
        cpa16(sbase + ABYTES + so, Bh + (size_t)rb * ldb + k0 + g * 8, pb);
        if constexpr (TERMS == 3)
            cpa16(sbase + ABYTES + NBT * 16384 + so, Bl + (size_t)rb * ldb + k0 + g * 8, pb);
    }
    cp_commit();
}

template<int TERMS, int BN, int HOUT>
__global__ __launch_bounds__(512, 1) void gemm_h(
    const __half* __restrict__ Ah, const __half* __restrict__ Al,
    int lda, long long sA,
    const __half* __restrict__ Bh, const __half* __restrict__ Bl,
    int ldb, long long sB,
    void* __restrict__ Cv, int ldc, long long sC, int zdiv, long long sC2,
    const float* __restrict__ R, int ldr, long long sR,
    int M, int N, int K, float alpha, int causal)
{
    constexpr int OPS = (TERMS == 3) ? 2 : 1;
    constexpr int ABYTES = 16384 * OPS;
    constexpr int NBT = BN / 128;
    constexpr int STAGE = ABYTES + NBT * 16384 * OPS;
    constexpr int NST = (TERMS == 1) ? 4 : 3;
    constexpr int NG4 = BN / 64;
    constexpr int NS  = BN / 32;

    extern __shared__ __align__(1024) char smem[];
    const uint32_t sb0 = smem_u32(smem);
    const int tid = threadIdx.x;
    const int wid = tid >> 5, lane = tid & 31;
    long long z = blockIdx.z;
    Ah += z * sA;
    if constexpr (TERMS == 3) Al += z * sA;
    Bh += z * sB;
    if constexpr (TERMS == 3) Bl += z * sB;
    if (R) R += z * sR;
    const long long zo = (z / zdiv) * sC + (z % zdiv) * sC2;
    const int bm = blockIdx.y * 128, bn = blockIdx.x * BN;
    const int wm = (wid >> 2) * 32, wn = (wid & 3) * (BN / 4);

    if (causal == 1 && bn > bm + 127) return;

    float acc[2][NS][4];
    #pragma unroll
    for (int i = 0; i < 2; i++)
        #pragma unroll
        for (int j = 0; j < NS; j++)
            #pragma unroll
            for (int r = 0; r < 4; r++) acc[i][j][r] = 0.f;

    int nc = K >> 6;
    if (causal == 2) { int lim = (bm + 191) >> 6; if (lim < nc) nc = lim; }

    #pragma unroll
    for (int s = 0; s < NST - 1; s++) {
        if (s < nc)
            issue_h<TERMS, BN>(sb0 + s * STAGE, Ah, Al, Bh, Bl, lda, ldb, bm, bn, M, N, s << 6, tid);
        else
            cp_commit();
    }

    const int arow = wm + (lane & 15);
    const int acb  = (lane >> 4) << 4;
    const int brow4 = wn + ((lane >> 4) << 3) + (lane & 7);
    const int bcb4  = ((lane >> 3) & 1) << 4;

    uint32_t ahf[2][4], alf[2][4];
    uint32_t bhf[NG4][4], blf[NG4][4];
    (void)alf; (void)blf;

    for (int c = 0; c < nc; c++) {
        cp_wait<NST - 2>();
        __syncthreads();
        {
            int nx = c + NST - 1;
            if (nx < nc)
                issue_h<TERMS, BN>(sb0 + (nx % NST) * STAGE, Ah, Al, Bh, Bl,
                                   lda, ldb, bm, bn, M, N, nx << 6, tid);
            else
                cp_commit();
        }

        uint32_t tA  = sb0 + (c % NST) * STAGE;
        uint32_t tAl = tA + 16384;
        uint32_t tB  = tA + ABYTES;
        uint32_t tBl = tB + NBT * 16384;

        #pragma unroll
        for (int ks = 0; ks < 4; ks++) {
            #pragma unroll
            for (int ms = 0; ms < 2; ms++) {
                uint32_t off = SW128((arow + ms * 16) * 128 + ks * 32 + acb);
                ldsm_x4(ahf[ms], tA + off);
                if constexpr (TERMS == 3) ldsm_x4(alf[ms], tAl + off);
            }
            #pragma unroll
            for (int ng4 = 0; ng4 < NG4; ng4++) {
                uint32_t off = SW128((brow4 + ng4 * 16) * 128 + ks * 32 + bcb4);
                ldsm_x4(bhf[ng4], tB + off);
                if constexpr (TERMS == 3) ldsm_x4(blf[ng4], tBl + off);
            }
            #pragma unroll
            for (int ng4 = 0; ng4 < NG4; ng4++)
                #pragma unroll
                for (int ms = 0; ms < 2; ms++) {
                    mma_f16(acc[ms][2*ng4],   ahf[ms], bhf[ng4]);
                    mma_f16(acc[ms][2*ng4+1], ahf[ms], bhf[ng4] + 2);
                    if constexpr (TERMS == 3) {
                        mma_f16(acc[ms][2*ng4],   ahf[ms], blf[ng4]);
                        mma_f16(acc[ms][2*ng4+1], ahf[ms], blf[ng4] + 2);
                        mma_f16(acc[ms][2*ng4],   alf[ms], bhf[ng4]);
                        mma_f16(acc[ms][2*ng4+1], alf[ms], bhf[ng4] + 2);
                    }
                }
        }
    }

    const int gid = lane >> 2, tc = lane & 3;
    if constexpr (HOUT == 2) {
        __half* C = (__half*)Cv + zo;
        #pragma unroll
        for (int ms = 0; ms < 2; ms++)
            #pragma unroll
            for (int ns = 0; ns < NS; ns++) {
                int gr0 = bm + wm + ms * 16 + gid;
                int gc  = bn + wn + ns * 8 + tc * 2;
                float g0 = acc[ms][ns][0], u0 = acc[ms][ns][1];
                float g1 = acc[ms][ns][2], u1 = acc[ms][ns][3];
                float r0 = g0 / (1.f + __expf(-g0)) * u0;
                float r1 = g1 / (1.f + __expf(-g1)) * u1;
                C[(size_t)gr0 * ldc + (gc >> 1)]       = __float2half_rn(r0);
                C[(size_t)(gr0 + 8) * ldc + (gc >> 1)] = __float2half_rn(r1);
            }
    } else if constexpr (HOUT == 1) {
        __half* C = (__half*)Cv + zo;
        #pragma unroll
        for (int ms = 0; ms < 2; ms++)
            #pragma unroll
            for (int ns = 0; ns < NS; ns++) {
                int gr0 = bm + wm + ms * 16 + gid;
                int gc  = bn + wn + ns * 8 + tc * 2;
                if (gc < N) {
                    *(__half2*)&C[(size_t)gr0 * ldc + gc] =
                        __floats2half2_rn(alpha * acc[ms][ns][0], alpha * acc[ms][ns][1]);
                    *(__half2*)&C[(size_t)(gr0 + 8) * ldc + gc] =
                        __floats2half2_rn(alpha * acc[ms][ns][2], alpha * acc[ms][ns][3]);
                }
            }
    } else {
        float* C = (float*)Cv + zo;
        #pragma unroll
        for (int ms = 0; ms < 2; ms++)
            #pragma unroll
            for (int ns = 0; ns < NS; ns++) {
                int gr0 = bm + wm + ms * 16 + gid;
                int gc  = bn + wn + ns * 8 + tc * 2;
                if (gc < N) {
                    float2 v0;
                    v0.x = alpha * acc[ms][ns][0];
                    v0.y = alpha * acc[ms][ns][1];
                    if (R) { v0.x += R[(size_t)gr0 * ldr + gc]; v0.y += R[(size_t)gr0 * ldr + gc + 1]; }
                    *(float2*)&C[(size_t)gr0 * ldc + gc] = v0;
                    int gr1 = gr0 + 8;
                    float2 v1;
                    v1.x = alpha * acc[ms][ns][2];
                    v1.y = alpha * acc[ms][ns][3];
                    if (R) { v1.x += R[(size_t)gr1 * ldr + gc]; v1.y += R[(size_t)gr1 * ldr + gc + 1]; }
                    *(float2*)&C[(size_t)gr1 * ldc + gc] = v1;
                }
            }
    }
}

#define SM_3_128 (3*(32768+32768))
#define SM_1_256 (4*(16384+32768))
#define SM_1_128 (4*(16384+16384))

// ------------------------------ host launch ---------------------------------
static void gemm3_s(cudaStream_t st,
                    const __half* Ah, const __half* Al, int lda, long long sA,
                    const __half* Bh, const __half* Bl, int ldb, long long sB,
                    float* C, int ldc, long long sC,
                    const float* R, int ldr, long long sR,
                    int M, int N, int K, float alpha, int Z, int causal = 0)
{
    dim3 grid((N + 127) / 128, M / 128, Z);
    gemm_h<3,128,0><<<grid, 512, SM_3_128, st>>>(Ah, Al, lda, sA, Bh, Bl, ldb, sB,
                                                 C, ldc, sC, 1, 0, R, ldr, sR, M, N, K, alpha, causal);
}
static void gemm1f(const __half* A, int lda, long long sA,
                   const __half* B, int ldb, long long sB,
                   float* C, int ldc, long long sC,
                   const float* R, int ldr, long long sR,
                   int M, int N, int K, float alpha, int Z, int causal = 0)
{
    if (N % 256 == 0) {
        dim3 grid(N / 256, M / 128, Z);
        gemm_h<1,256,0><<<grid, 512, SM_1_256>>>(A, nullptr, lda, sA, B, nullptr, ldb, sB,
                                                 C, ldc, sC, 1, 0, R, ldr, sR, M, N, K, alpha, causal);
    } else {
        dim3 grid((N + 127) / 128, M / 128, Z);
        gemm_h<1,128,0><<<grid, 512, SM_1_128>>>(A, nullptr, lda, sA, B, nullptr, ldb, sB,
                                                 C, ldc, sC, 1, 0, R, ldr, sR, M, N, K, alpha, causal);
    }
}

static void splitp_s(cudaStream_t st, const float* in, __half* hi, __half* lo, long long n)
{
    long long n4 = n >> 2;
    split_h_k<<<(unsigned)((n4 + 255) / 256), 256, 0, st>>>(
        (const float4*)in, (__half2*)hi, (__half2*)lo, n4);
}

// streams/events created ONCE (first call = correctness run, before the
// harness's pre-capture memory baseline) and reused by every capture call.
static cudaStream_t g_s1 = nullptr, g_s2 = nullptr;
static cudaEvent_t  g_evFork, g_evQKA, g_evQB, g_evKB, g_evConv, g_evQKVA, g_evKV;

extern "C" void kernel_launch(void* const* d_in, const int* in_sizes, int n_in,
                              void* d_out, int out_size)
{
    const float* x     = (const float*)d_in[0];
    const float* mask  = (const float*)d_in[1];
    const float* fcos  = (const float*)d_in[2];
    const float* fsin  = (const float*)d_in[3];
    const float* anw   = (const float*)d_in[4];
    const float* wq_a  = (const float*)d_in[5];
    const float* qnw   = (const float*)d_in[6];
    const float* wq_b  = (const float*)d_in[7];
    const float* wkv_a = (const float*)d_in[8];
    const float* kvnw  = (const float*)d_in[9];
    const float* wkv_b = (const float*)d_in[10];
    const float* wo    = (const float*)d_in[11];
    const float* fnw   = (const float*)d_in[12];
    const float* w1    = (const float*)d_in[13];
    const float* w2    = (const float*)d_in[14];
    const float* w3    = (const float*)d_in[15];
    float* out = (float*)d_out;

    if (!g_s1) {
        cudaStreamCreateWithFlags(&g_s1, cudaStreamNonBlocking);
        cudaStreamCreateWithFlags(&g_s2, cudaStreamNonBlocking);
        cudaEventCreateWithFlags(&g_evFork, cudaEventDisableTiming);
        cudaEventCreateWithFlags(&g_evQKA,  cudaEventDisableTiming);
        cudaEventCreateWithFlags(&g_evQB,   cudaEventDisableTiming);
        cudaEventCreateWithFlags(&g_evKB,   cudaEventDisableTiming);
        cudaEventCreateWithFlags(&g_evConv, cudaEventDisableTiming);
        cudaEventCreateWithFlags(&g_evQKVA, cudaEventDisableTiming);
        cudaEventCreateWithFlags(&g_evKV,   cudaEventDisableTiming);
        cudaFuncSetAttribute(gemm_h<3,128,0>, cudaFuncAttributeMaxDynamicSharedMemorySize, SM_3_128);
        cudaFuncSetAttribute(gemm_h<1,256,0>, cudaFuncAttributeMaxDynamicSharedMemorySize, SM_1_256);
        cudaFuncSetAttribute(gemm_h<1,128,0>, cudaFuncAttributeMaxDynamicSharedMemorySize, SM_1_128);
        cudaFuncSetAttribute(gemm_h<1,128,1>, cudaFuncAttributeMaxDynamicSharedMemorySize, SM_1_128);
        cudaFuncSetAttribute(gemm_h<1,256,2>, cudaFuncAttributeMaxDynamicSharedMemorySize, SM_1_256);
    }
    cudaStream_t s1 = g_s1, s2 = g_s2;

    float *p_qkva, *p_q, *p_kv, *p_sc, *p_x2;
    cudaGetSymbolAddress((void**)&p_qkva, g_qkva);
    cudaGetSymbolAddress((void**)&p_q,    g_q);
    cudaGetSymbolAddress((void**)&p_kv,   g_kv);
    cudaGetSymbolAddress((void**)&p_sc,   g_sc);
    cudaGetSymbolAddress((void**)&p_x2,   g_x2);

    __half *hH,*hL,*qaH,*qaL,*kvnH,*kvnL,*qfH,*qfL,*kfH,*kfL,*vT,*at,*y2,*h2,*gs,
           *wqkaH,*wqkaL,*wqbH,*wqbL,*wkbH,*wkbL,*woh,*w13h,*w2h;
    cudaGetSymbolAddress((void**)&hH,   f_hH);  cudaGetSymbolAddress((void**)&hL,   f_hL);
    cudaGetSymbolAddress((void**)&qaH,  f_qaH); cudaGetSymbolAddress((void**)&qaL,  f_qaL);
    cudaGetSymbolAddress((void**)&kvnH, f_kvnH);cudaGetSymbolAddress((void**)&kvnL, f_kvnL);
    cudaGetSymbolAddress((void**)&qfH,  f_qfH); cudaGetSymbolAddress((void**)&qfL,  f_qfL);
    cudaGetSymbolAddress((void**)&kfH,  f_kfH); cudaGetSymbolAddress((void**)&kfL,  f_kfL);
    cudaGetSymbolAddress((void**)&vT,   f_vT);  cudaGetSymbolAddress((void**)&at,   f_at);
    cudaGetSymbolAddress((void**)&y2,   f_y2);
    cudaGetSymbolAddress((void**)&h2,   f_h2);  cudaGetSymbolAddress((void**)&gs,   f_gs);
    cudaGetSymbolAddress((void**)&wqkaH,f_wqkaH);cudaGetSymbolAddress((void**)&wqkaL,f_wqkaL);
    cudaGetSymbolAddress((void**)&wqbH, f_wqbH);cudaGetSymbolAddress((void**)&wqbL, f_wqbL);
    cudaGetSymbolAddress((void**)&wkbH, f_wkbH);cudaGetSymbolAddress((void**)&wkbL, f_wkbL);
    cudaGetSymbolAddress((void**)&woh,  f_wo);
    cudaGetSymbolAddress((void**)&w13h, f_w13); cudaGetSymbolAddress((void**)&w2h,  f_w2);

    cudaEventRecord(g_evFork, 0);
    cudaStreamWaitEvent(s1, g_evFork, 0);

    // s1: weight conversions
    splitp_s(s1, wq_a,  wqkaH, wqkaL, (long long)CQLORA*CD);
    splitp_s(s1, wkv_a, wqkaH + (long long)CQLORA*CD, wqkaL + (long long)CQLORA*CD,
             (long long)(CKVLORA+CROPE)*CD);
    cudaEventRecord(g_evQKA, s1);
    splitp_s(s1, wq_b, wqbH, wqbL, (long long)CH*CQKD*CQLORA);
    cudaEventRecord(g_evQB, s1);
    splitp_s(s1, wkv_b, wkbH, wkbL, (long long)CH*256*CKVLORA);
    cudaEventRecord(g_evKB, s1);
    {
        long long n4big = ((long long)CINTER * CD) >> 2;
        long long n4wo  = ((long long)CD * CD) >> 2;
        dim3 grid((unsigned)((n4big + 255) / 256), 4);
        conv4_h_k<<<grid, 256, 0, s1>>>((const float4*)w1, (const float4*)w3,
                                        (const float4*)w2, (const float4*)wo,
                                        (__half2*)w13h, (__half2*)w2h, (__half2*)woh,
                                        n4big, n4wo);
    }
    cudaEventRecord(g_evConv, s1);

    // ---- main stream: attention path ----
    rmsnorm_split_h_k<<<CM, 256>>>(x, CD, anw, hH, hL, CD);
    cudaStreamWaitEvent(0, g_evQKA, 0);
    // qkva = h @ [wq_a; wkv_a]^T
    gemm3_s(0, hH, hL, CD, 0, wqkaH, wqkaL, CD, 0, p_qkva, NQKVA, 0,
            nullptr, 0, 0, CM, NQKVA, CD, 1.f, 1);
    cudaEventRecord(g_evQKVA, 0);

    // s2: kv path (norm + kv GEMM) in parallel with main's q path
    cudaStreamWaitEvent(s2, g_evQKVA, 0);
    cudaStreamWaitEvent(s2, g_evKB, 0);
    rmsnorm_split_h_k<<<CM, 256, 0, s2>>>(p_qkva + CQLORA, NQKVA, kvnw, kvnH, kvnL, CKVLORA);
    gemm3_s(s2, kvnH, kvnL, CKVLORA, 0, wkbH, wkbL, CKVLORA, 0, p_kv, CH*256, 0,
            nullptr, 0, 0, CM, CH*256, CKVLORA, 1.f, 1);
    cudaEventRecord(g_evKV, s2);

    // main: q path
    rmsnorm_split_h_k<<<CM, 256>>>(p_qkva, NQKVA, qnw, qaH, qaL, CQLORA);
    cudaStreamWaitEvent(0, g_evQB, 0);
    gemm3_s(0, qaH, qaL, CQLORA, 0, wqbH, wqbL, CQLORA, 0, p_q, CH*CQKD, 0,
            nullptr, 0, 0, CM, CH*CQKD, CQLORA, 1.f, 1);

    // join kv path, then rope
    cudaStreamWaitEvent(0, g_evKV, 0);
    rope_pack_h_k<<<dim3(CT, CB), 256>>>(p_q, p_kv, p_qkva, fcos, fsin,
                                         qfH, qfL, kfH, kfL, vT);
    // scores = -96 * qf @ kf^T + mask (masked tiles skipped; softmax fills zeros)
    gemm3_s(0, qfH, qfL, CQKD, (long long)CT*CQKD,
            kfH, kfL, CQKD, (long long)CT*CQKD,
            p_sc, CT, (long long)CT*CT,
            mask, CT, 0, CT, CT, CQKD, -96.f, CB*CH, 1);
    softmax_causal_h_k<<<CB*CH*CT, 256>>>(p_sc, at);
    // y2 = attn @ vT with fused [B,H,T,d] -> [B*T, H*d] permute in epilogue
    {
        dim3 grid(1, CT / 128, CB*CH);
        gemm_h<1,128,1><<<grid, 512, SM_1_128>>>(
            at, nullptr, CT, (long long)CT*CT,
            vT, nullptr, CT, (long long)CVHD*CT,
            y2, CD, (long long)CT*CD, CH, (long long)CVHD,
            nullptr, 0, 0, CT, CVHD, CT, 1.f, 2);
    }
    // join conversion stream before first consumer of woh/w13h/w2h
    cudaStreamWaitEvent(0, g_evConv, 0);
    // x2 = x + y2 @ wo^T
    gemm1f(y2, CH*CVHD, 0, woh, CH*CVHD, 0, p_x2, CD, 0,
           x, CD, 0, CM, CD, CH*CVHD, 1.f, 1);

    // ---- FFN path ----
    rmsnorm_h_k<<<CM, 256>>>(p_x2, CD, fnw, h2, CD);
    // gs = silu(h2@w1^T) * (h2@w3^T) in ONE GEMM (w13 interleaved, fused epilogue)
    {
        dim3 grid((2*CINTER) / 256, CM / 128, 1);
        gemm_h<1,256,2><<<grid, 512, SM_1_256>>>(
            h2, nullptr, CD, 0,
            w13h, nullptr, CD, 0,
            gs, CINTER, 0, 1, 0,
            nullptr, 0, 0, CM, 2*CINTER, CD, 1.f, 0);
    }
    // out = x2 + gs @ w2^T
    gemm1f(gs, CINTER, 0, w2h, CINTER, 0, out, CD, 0,
           p_x2, CD, 0, CM, CD, CINTER, 1.f, 1);
}

// round 16
// speedup vs baseline: 1.0858x; 1.0220x over previous
#include <cuda_runtime.h>
#include <cuda_fp16.h>
#include <cstdint>

// ---------------------------------------------------------------------------
// DeepSeek MLA block on GB300 — mma.sync fp16 GEMMs, v14.
// q/k path: fp16-pair 3-term split. Additive paths: 1-term fp16.
// v14 = v13 with the maskless-softmax boundary-quad fix: elements j > sIdx
//       inside the diagonal float4 are forced to -1e30 (exp -> 0 exactly,
//       matching the reference's additive -1e9 mask).
// ---------------------------------------------------------------------------

#define CB 2
#define CT 1024
#define CD 2048
#define CH 16
#define CNOPE 128
#define CROPE 64
#define CQKD 192
#define CQLORA 1536
#define CKVLORA 512
#define CVHD 128
#define CINTER 8192
#define CM (CB*CT)
#define NQKVA (CQLORA + CKVLORA + CROPE)   // 2112

// ------------------------------- PTX helpers -------------------------------
__device__ __forceinline__ uint32_t smem_u32(const void* p) {
    uint32_t a;
    asm("{ .reg .u64 t; cvta.to.shared.u64 t, %1; cvt.u32.u64 %0, t; }" : "=r"(a) : "l"(p));
    return a;
}
#define SW128(o) ((o) ^ (((o) >> 3) & 0x70))

__device__ __forceinline__ void cpa16(uint32_t s, const void* g, int sz) {
    asm volatile("cp.async.cg.shared.global [%0], [%1], 16, %2;"
                 :: "r"(s), "l"(g), "r"(sz));
}
__device__ __forceinline__ void cp_commit() {
    asm volatile("cp.async.commit_group;" ::: "memory");
}
template <int N> __device__ __forceinline__ void cp_wait() {
    asm volatile("cp.async.wait_group %0;" :: "n"(N) : "memory");
}
__device__ __forceinline__ void ldsm_x4(uint32_t* r, uint32_t a) {
    asm volatile("ldmatrix.sync.aligned.m8n8.x4.shared.b16 {%0,%1,%2,%3}, [%4];"
        : "=r"(r[0]), "=r"(r[1]), "=r"(r[2]), "=r"(r[3]) : "r"(a));
}
__device__ __forceinline__ void mma_f16(float* d, const uint32_t* a, const uint32_t* b) {
    asm volatile(
        "mma.sync.aligned.m16n8k16.row.col.f32.f16.f16.f32 "
        "{%0,%1,%2,%3}, {%4,%5,%6,%7}, {%8,%9}, {%0,%1,%2,%3};"
        : "+f"(d[0]), "+f"(d[1]), "+f"(d[2]), "+f"(d[3])
        : "r"(a[0]), "r"(a[1]), "r"(a[2]), "r"(a[3]), "r"(b[0]), "r"(b[1]));
}

// ------------------------- scratch (device globals) ------------------------
__device__ float g_qkva[(long long)CM*NQKVA];
__device__ float g_q   [(long long)CM*CH*CQKD];
__device__ float g_kv  [(long long)CM*CH*(CNOPE+CVHD)];
__device__ float g_sc  [(long long)CB*CH*CT*CT];
__device__ float g_x2  [(long long)CM*CD];

// fp16 operand buffers
__device__ __half f_hH [(long long)CM*CD],        f_hL [(long long)CM*CD];
__device__ __half f_qaH[(long long)CM*CQLORA],    f_qaL[(long long)CM*CQLORA];
__device__ __half f_kvnH[(long long)CM*CKVLORA],  f_kvnL[(long long)CM*CKVLORA];
__device__ __half f_qfH[(long long)CB*CH*CT*CQKD], f_qfL[(long long)CB*CH*CT*CQKD];
__device__ __half f_kfH[(long long)CB*CH*CT*CQKD], f_kfL[(long long)CB*CH*CT*CQKD];
__device__ __half f_vT [(long long)CB*CH*CVHD*CT];
__device__ __half f_at [(long long)CB*CH*CT*CT];
__device__ __half f_y2 [(long long)CM*CD];
__device__ __half f_h2 [(long long)CM*CD];
__device__ __half f_gs [(long long)CM*CINTER];
// weights
__device__ __half f_wqkaH[(long long)NQKVA*CD],   f_wqkaL[(long long)NQKVA*CD];
__device__ __half f_wqbH[(long long)CH*CQKD*CQLORA], f_wqbL[(long long)CH*CQKD*CQLORA];
__device__ __half f_wkbH[(long long)CH*256*CKVLORA], f_wkbL[(long long)CH*256*CKVLORA];
__device__ __half f_wo [(long long)CD*CD];
__device__ __half f_w13[(long long)2*CINTER*CD];   // interleaved: row 2j=w1_j, 2j+1=w3_j
__device__ __half f_w2 [(long long)CD*CINTER];

// ------------------------------- split helpers -----------------------------
__device__ __forceinline__ void split1h(float v, __half& h, __half& l) {
    h = __float2half_rn(v);
    l = __float2half_rn(v - __half2float(h));
}

__global__ __launch_bounds__(256) void split_h_k(
    const float4* __restrict__ in, __half2* __restrict__ hi,
    __half2* __restrict__ lo, long long n4)
{
    long long i = (long long)blockIdx.x * 256 + threadIdx.x;
    if (i >= n4) return;
    float4 v = in[i];
    __half h0,h1,h2,h3,l0,l1,l2,l3;
    split1h(v.x,h0,l0); split1h(v.y,h1,l1); split1h(v.z,h2,l2); split1h(v.w,h3,l3);
    hi[2*i]   = __halves2half2(h0,h1);
    hi[2*i+1] = __halves2half2(h2,h3);
    lo[2*i]   = __halves2half2(l0,l1);
    lo[2*i+1] = __halves2half2(l2,l3);
}

// convert w1 (interleave even rows), w3 (odd rows), w2 (straight), wo (straight)
__global__ __launch_bounds__(256) void conv4_h_k(
    const float4* __restrict__ w1, const float4* __restrict__ w3,
    const float4* __restrict__ w2, const float4* __restrict__ wo,
    __half2* __restrict__ w13, __half2* __restrict__ w2h, __half2* __restrict__ woh,
    long long n4big, long long n4wo)
{
    long long i = (long long)blockIdx.x * 256 + threadIdx.x;
    int which = blockIdx.y;
    if (which <= 1) {
        if (i >= n4big) return;
        const float4* s = which ? w3 : w1;
        float4 v = s[i];
        long long row = i / (CD/4), off = i % (CD/4);
        long long orow = 2*row + which;
        __half2* d = w13 + orow * (CD/2) + off*2;
        d[0] = __floats2half2_rn(v.x, v.y);
        d[1] = __floats2half2_rn(v.z, v.w);
    } else if (which == 2) {
        if (i >= n4big) return;
        float4 v = w2[i];
        w2h[2*i]   = __floats2half2_rn(v.x, v.y);
        w2h[2*i+1] = __floats2half2_rn(v.z, v.w);
    } else {
        if (i >= n4wo) return;
        float4 v = wo[i];
        woh[2*i]   = __floats2half2_rn(v.x, v.y);
        woh[2*i+1] = __floats2half2_rn(v.z, v.w);
    }
}

// ------------------------------ RMSNorm variants ----------------------------
__device__ __forceinline__ float rms_scale(const float* ip, int K, int tid) {
    float s = 0.f;
    for (int i = tid; i < K; i += 256) { float v = ip[i]; s += v * v; }
    __shared__ float red[32];
    #pragma unroll
    for (int o = 16; o > 0; o >>= 1) s += __shfl_xor_sync(0xffffffffu, s, o);
    int warp = tid >> 5, lane = tid & 31;
    if (lane == 0) red[warp] = s;
    __syncthreads();
    if (warp == 0) {
        float s2 = (lane < 8) ? red[lane] : 0.f;
        #pragma unroll
        for (int o = 4; o > 0; o >>= 1) s2 += __shfl_xor_sync(0xffffffffu, s2, o);
        if (lane == 0) red[0] = s2;
    }
    __syncthreads();
    return rsqrtf(red[0] / (float)K + 1e-6f);
}

__global__ __launch_bounds__(256) void rmsnorm_split_h_k(
    const float* __restrict__ in, int ldin, const float* __restrict__ w,
    __half* __restrict__ hi, __half* __restrict__ lo, int K)
{
    long long row = blockIdx.x;
    const float* ip = in + row * ldin;
    float scale = rms_scale(ip, K, threadIdx.x);
    for (int i = threadIdx.x; i < K; i += 256) {
        float v = ip[i] * scale * w[i];
        __half h, l; split1h(v, h, l);
        hi[row * (long long)K + i] = h;
        lo[row * (long long)K + i] = l;
    }
}

__global__ __launch_bounds__(256) void rmsnorm_h_k(
    const float* __restrict__ in, int ldin, const float* __restrict__ w,
    __half* __restrict__ out, int K)
{
    long long row = blockIdx.x;
    const float* ip = in + row * ldin;
    float scale = rms_scale(ip, K, threadIdx.x);
    for (int i = threadIdx.x; i < K; i += 256)
        out[row * (long long)K + i] = __float2half_rn(ip[i] * scale * w[i]);
}

// ------------------- RoPE + head packing (qf/kf pairs, vT single) -----------
__global__ __launch_bounds__(256) void rope_pack_h_k(
    const float* __restrict__ q, const float* __restrict__ kv,
    const float* __restrict__ qkva,
    const float* __restrict__ fcos, const float* __restrict__ fsin,
    __half* __restrict__ qfH, __half* __restrict__ qfL,
    __half* __restrict__ kfH, __half* __restrict__ kfL,
    __half* __restrict__ vT)
{
    int t = blockIdx.x, b = blockIdx.y;
    long long m = (long long)b * CT + t;
    __shared__ float kpe[CROPE], cs[32], sn[32];
    int tid = threadIdx.x;
    if (tid < 32) { cs[tid] = fcos[t*32 + tid]; sn[tid] = fsin[t*32 + tid]; }
    __syncthreads();
    if (tid < 32) {
        float x0 = qkva[m*NQKVA + 2048 + 2*tid];
        float x1 = qkva[m*NQKVA + 2048 + 2*tid + 1];
        kpe[2*tid]   = x0*cs[tid] - x1*sn[tid];
        kpe[2*tid+1] = x0*sn[tid] + x1*cs[tid];
    }
    __syncthreads();
    for (int idx = tid; idx < CH*CQKD; idx += 256) {
        int h = idx / CQKD, d = idx % CQKD;
        long long o = (((long long)b*CH + h)*CT + t)*CQKD + d;
        float qv, kvv;
        if (d < CNOPE) {
            qv  = q [m*(CH*CQKD) + h*CQKD + d];
            kvv = kv[m*(CH*256)  + h*256  + d];
        } else {
            int j = d - CNOPE, i2 = j >> 1;
            float x0 = q[m*(CH*CQKD) + h*CQKD + CNOPE + 2*i2];
            float x1 = q[m*(CH*CQKD) + h*CQKD + CNOPE + 2*i2 + 1];
            qv  = (j & 1) ? (x0*sn[i2] + x1*cs[i2]) : (x0*cs[i2] - x1*sn[i2]);
            kvv = kpe[j];
        }
        __half hh, ll;
        split1h(qv, hh, ll);  qfH[o] = hh; qfL[o] = ll;
        split1h(kvv, hh, ll); kfH[o] = hh; kfL[o] = ll;
    }
    for (int idx = tid; idx < CH*CVHD; idx += 256) {
        int h = idx >> 7, d = idx & 127;
        vT[(((long long)b*CH + h)*CVHD + d)*CT + t] =
            __float2half_rn(kv[m*(CH*256) + h*256 + CNOPE + d]);
    }
}

// ------ causal softmax (fp16 out, maskless: per-element boundary masking) ----
__global__ __launch_bounds__(256) void softmax_causal_h_k(
    const float* __restrict__ s, __half* __restrict__ at)
{
    long long row = blockIdx.x;
    int sIdx = (int)(row & (CT - 1));
    const float4* p = (const float4*)(s + row * (long long)CT);
    int tid = threadIdx.x, warp = tid >> 5, lane = tid & 31;
    __shared__ float red[32];

    int base = 4 * tid;
    bool act = (base <= sIdx);
    float4 v = make_float4(-1e30f, -1e30f, -1e30f, -1e30f);
    if (act) {
        v = p[tid];
        // boundary quad: mask elements beyond the diagonal (mask was -1e9 there)
        if (base + 1 > sIdx) v.y = -1e30f;
        if (base + 2 > sIdx) v.z = -1e30f;
        if (base + 3 > sIdx) v.w = -1e30f;
    }
    float mx = fmaxf(fmaxf(v.x, v.y), fmaxf(v.z, v.w));
    #pragma unroll
    for (int o = 16; o > 0; o >>= 1) mx = fmaxf(mx, __shfl_xor_sync(0xffffffffu, mx, o));
    if (lane == 0) red[warp] = mx;
    __syncthreads();
    if (warp == 0) {
        float m2 = (lane < 8) ? red[lane] : -1e30f;
        #pragma unroll
        for (int o = 4; o > 0; o >>= 1) m2 = fmaxf(m2, __shfl_xor_sync(0xffffffffu, m2, o));
        if (lane == 0) red[0] = m2;
    }
    __syncthreads();
    mx = red[0];
    __syncthreads();

    float sum = 0.f;
    if (act) {
        v.x = __expf(v.x - mx); v.y = __expf(v.y - mx);
        v.z = __expf(v.z - mx); v.w = __expf(v.w - mx);
        sum = v.x + v.y + v.z + v.w;
    }
    #pragma unroll
    for (int o = 16; o > 0; o >>= 1) sum += __shfl_xor_sync(0xffffffffu, sum, o);
    if (lane == 0) red[warp] = sum;
    __syncthreads();
    if (warp == 0) {
        float s2 = (lane < 8) ? red[lane] : 0.f;
        #pragma unroll
        for (int o = 4; o > 0; o >>= 1) s2 += __shfl_xor_sync(0xffffffffu, s2, o);
        if (lane == 0) red[0] = s2;
    }
    __syncthreads();
    float inv = 1.f / red[0];
    __half2* H = (__half2*)(at + row * (long long)CT);
    if (act) {
        H[2*tid]   = __floats2half2_rn(v.x * inv, v.y * inv);
        H[2*tid+1] = __floats2half2_rn(v.z * inv, v.w * inv);
    } else {
        H[2*tid]   = __halves2half2(__float2half_rn(0.f), __float2half_rn(0.f));
        H[2*tid+1] = H[2*tid];
    }
}

// ======================= templated fp16 HMMA GEMM (512 thr) =================
template<int TERMS, int BN>
__device__ __forceinline__ void issue_h(
    uint32_t sbase, const __half* Ah, const __half* Al,
    const __half* Bh, const __half* Bl,
    int lda, int ldb, int bm, int bn, int M, int N, int k0, int tid)
{
    constexpr int OPS = (TERMS == 3) ? 2 : 1;
    constexpr int ABYTES = 16384 * OPS;
    constexpr int NBT = BN / 128;
    #pragma unroll
    for (int it = 0; it < 2; it++) {
        int e = it * 512 + tid;
        int r = e >> 3, g = e & 7;
        uint32_t so = SW128(r * 128 + g * 16);
        int ra = bm + r; int pa = (ra < M) ? 16 : 0; if (!pa) ra = 0;
        cpa16(sbase + so, Ah + (size_t)ra * lda + k0 + g * 8, pa);
        if constexpr (TERMS == 3)
            cpa16(sbase + 16384 + so, Al + (size_t)ra * lda + k0 + g * 8, pa);
    }
    #pragma unroll
    for (int it = 0; it < 2 * NBT; it++) {
        int e = it * 512 + tid;
        int r = e >> 3, g = e & 7;
        uint32_t so = SW128(r * 128 + g * 16);
        int rb = bn + r; int pb = (rb < N) ? 16 : 0; if (!pb) rb = 0;
        cpa16(sbase + ABYTES + so, Bh + (size_t)rb * ldb + k0 + g * 8, pb);
        if constexpr (TERMS == 3)
            cpa16(sbase + ABYTES + NBT * 16384 + so, Bl + (size_t)rb * ldb + k0 + g * 8, pb);
    }
    cp_commit();
}

template<int TERMS, int BN, int HOUT>
__global__ __launch_bounds__(512, 1) void gemm_h(
    const __half* __restrict__ Ah, const __half* __restrict__ Al,
    int lda, long long sA,
    const __half* __restrict__ Bh, const __half* __restrict__ Bl,
    int ldb, long long sB,
    void* __restrict__ Cv, int ldc, long long sC, int zdiv, long long sC2,
    const float* __restrict__ R, int ldr, long long sR,
    int M, int N, int K, float alpha, int causal)
{
    constexpr int OPS = (TERMS == 3) ? 2 : 1;
    constexpr int ABYTES = 16384 * OPS;
    constexpr int NBT = BN / 128;
    constexpr int STAGE = ABYTES + NBT * 16384 * OPS;
    constexpr int NST = (TERMS == 1) ? 4 : 3;
    constexpr int NG4 = BN / 64;
    constexpr int NS  = BN / 32;

    extern __shared__ __align__(1024) char smem[];
    const uint32_t sb0 = smem_u32(smem);
    const int tid = threadIdx.x;
    const int wid = tid >> 5, lane = tid & 31;
    long long z = blockIdx.z;
    Ah += z * sA;
    if constexpr (TERMS == 3) Al += z * sA;
    Bh += z * sB;
    if constexpr (TERMS == 3) Bl += z * sB;
    if (R) R += z * sR;
    const long long zo = (z / zdiv) * sC + (z % zdiv) * sC2;
    const int bm = blockIdx.y * 128, bn = blockIdx.x * BN;
    const int wm = (wid >> 2) * 32, wn = (wid & 3) * (BN / 4);

    if (causal == 1 && bn > bm + 127) return;

    float acc[2][NS][4];
    #pragma unroll
    for (int i = 0; i < 2; i++)
        #pragma unroll
        for (int j = 0; j < NS; j++)
            #pragma unroll
            for (int r = 0; r < 4; r++) acc[i][j][r] = 0.f;

    int nc = K >> 6;
    if (causal == 2) { int lim = (bm + 191) >> 6; if (lim < nc) nc = lim; }

    #pragma unroll
    for (int s = 0; s < NST - 1; s++) {
        if (s < nc)
            issue_h<TERMS, BN>(sb0 + s * STAGE, Ah, Al, Bh, Bl, lda, ldb, bm, bn, M, N, s << 6, tid);
        else
            cp_commit();
    }

    const int arow = wm + (lane & 15);
    const int acb  = (lane >> 4) << 4;
    const int brow4 = wn + ((lane >> 4) << 3) + (lane & 7);
    const int bcb4  = ((lane >> 3) & 1) << 4;

    uint32_t ahf[2][4], alf[2][4];
    uint32_t bhf[NG4][4], blf[NG4][4];
    (void)alf; (void)blf;

    for (int c = 0; c < nc; c++) {
        cp_wait<NST - 2>();
        __syncthreads();
        {
            int nx = c + NST - 1;
            if (nx < nc)
                issue_h<TERMS, BN>(sb0 + (nx % NST) * STAGE, Ah, Al, Bh, Bl,
                                   lda, ldb, bm, bn, M, N, nx << 6, tid);
            else
                cp_commit();
        }

        uint32_t tA  = sb0 + (c % NST) * STAGE;
        uint32_t tAl = tA + 16384;
        uint32_t tB  = tA + ABYTES;
        uint32_t tBl = tB + NBT * 16384;

        #pragma unroll
        for (int ks = 0; ks < 4; ks++) {
            #pragma unroll
            for (int ms = 0; ms < 2; ms++) {
                uint32_t off = SW128((arow + ms * 16) * 128 + ks * 32 + acb);
                ldsm_x4(ahf[ms], tA + off);
                if constexpr (TERMS == 3) ldsm_x4(alf[ms], tAl + off);
            }
            #pragma unroll
            for (int ng4 = 0; ng4 < NG4; ng4++) {
                uint32_t off = SW128((brow4 + ng4 * 16) * 128 + ks * 32 + bcb4);
                ldsm_x4(bhf[ng4], tB + off);
                if constexpr (TERMS == 3) ldsm_x4(blf[ng4], tBl + off);
            }
            #pragma unroll
            for (int ng4 = 0; ng4 < NG4; ng4++)
                #pragma unroll
                for (int ms = 0; ms < 2; ms++) {
                    mma_f16(acc[ms][2*ng4],   ahf[ms], bhf[ng4]);
                    mma_f16(acc[ms][2*ng4+1], ahf[ms], bhf[ng4] + 2);
                    if constexpr (TERMS == 3) {
                        mma_f16(acc[ms][2*ng4],   ahf[ms], blf[ng4]);
                        mma_f16(acc[ms][2*ng4+1], ahf[ms], blf[ng4] + 2);
                        mma_f16(acc[ms][2*ng4],   alf[ms], bhf[ng4]);
                        mma_f16(acc[ms][2*ng4+1], alf[ms], bhf[ng4] + 2);
                    }
                }
        }
    }

    const int gid = lane >> 2, tc = lane & 3;
    if constexpr (HOUT == 2) {
        __half* C = (__half*)Cv + zo;
        #pragma unroll
        for (int ms = 0; ms < 2; ms++)
            #pragma unroll
            for (int ns = 0; ns < NS; ns++) {
                int gr0 = bm + wm + ms * 16 + gid;
                int gc  = bn + wn + ns * 8 + tc * 2;
                float g0 = acc[ms][ns][0], u0 = acc[ms][ns][1];
                float g1 = acc[ms][ns][2], u1 = acc[ms][ns][3];
                float r0 = g0 / (1.f + __expf(-g0)) * u0;
                float r1 = g1 / (1.f + __expf(-g1)) * u1;
                C[(size_t)gr0 * ldc + (gc >> 1)]       = __float2half_rn(r0);
                C[(size_t)(gr0 + 8) * ldc + (gc >> 1)] = __float2half_rn(r1);
            }
    } else if constexpr (HOUT == 1) {
        __half* C = (__half*)Cv + zo;
        #pragma unroll
        for (int ms = 0; ms < 2; ms++)
            #pragma unroll
            for (int ns = 0; ns < NS; ns++) {
                int gr0 = bm + wm + ms * 16 + gid;
                int gc  = bn + wn + ns * 8 + tc * 2;
                if (gc < N) {
                    *(__half2*)&C[(size_t)gr0 * ldc + gc] =
                        __floats2half2_rn(alpha * acc[ms][ns][0], alpha * acc[ms][ns][1]);
                    *(__half2*)&C[(size_t)(gr0 + 8) * ldc + gc] =
                        __floats2half2_rn(alpha * acc[ms][ns][2], alpha * acc[ms][ns][3]);
                }
            }
    } else {
        float* C = (float*)Cv + zo;
        #pragma unroll
        for (int ms = 0; ms < 2; ms++)
            #pragma unroll
            for (int ns = 0; ns < NS; ns++) {
                int gr0 = bm + wm + ms * 16 + gid;
                int gc  = bn + wn + ns * 8 + tc * 2;
                if (gc < N) {
                    float2 v0;
                    v0.x = alpha * acc[ms][ns][0];
                    v0.y = alpha * acc[ms][ns][1];
                    if (R) { v0.x += R[(size_t)gr0 * ldr + gc]; v0.y += R[(size_t)gr0 * ldr + gc + 1]; }
                    *(float2*)&C[(size_t)gr0 * ldc + gc] = v0;
                    int gr1 = gr0 + 8;
                    float2 v1;
                    v1.x = alpha * acc[ms][ns][2];
                    v1.y = alpha * acc[ms][ns][3];
                    if (R) { v1.x += R[(size_t)gr1 * ldr + gc]; v1.y += R[(size_t)gr1 * ldr + gc + 1]; }
                    *(float2*)&C[(size_t)gr1 * ldc + gc] = v1;
                }
            }
    }
}

#define SM_3_128 (3*(32768+32768))
#define SM_1_256 (4*(16384+32768))
#define SM_1_128 (4*(16384+16384))

// ------------------------------ host launch ---------------------------------
static void gemm3_s(cudaStream_t st,
                    const __half* Ah, const __half* Al, int lda, long long sA,
                    const __half* Bh, const __half* Bl, int ldb, long long sB,
                    float* C, int ldc, long long sC,
                    const float* R, int ldr, long long sR,
                    int M, int N, int K, float alpha, int Z, int causal = 0)
{
    dim3 grid((N + 127) / 128, M / 128, Z);
    gemm_h<3,128,0><<<grid, 512, SM_3_128, st>>>(Ah, Al, lda, sA, Bh, Bl, ldb, sB,
                                                 C, ldc, sC, 1, 0, R, ldr, sR, M, N, K, alpha, causal);
}
static void gemm1f(const __half* A, int lda, long long sA,
                   const __half* B, int ldb, long long sB,
                   float* C, int ldc, long long sC,
                   const float* R, int ldr, long long sR,
                   int M, int N, int K, float alpha, int Z, int causal = 0)
{
    if (N % 256 == 0) {
        dim3 grid(N / 256, M / 128, Z);
        gemm_h<1,256,0><<<grid, 512, SM_1_256>>>(A, nullptr, lda, sA, B, nullptr, ldb, sB,
                                                 C, ldc, sC, 1, 0, R, ldr, sR, M, N, K, alpha, causal);
    } else {
        dim3 grid((N + 127) / 128, M / 128, Z);
        gemm_h<1,128,0><<<grid, 512, SM_1_128>>>(A, nullptr, lda, sA, B, nullptr, ldb, sB,
                                                 C, ldc, sC, 1, 0, R, ldr, sR, M, N, K, alpha, causal);
    }
}

static void splitp_s(cudaStream_t st, const float* in, __half* hi, __half* lo, long long n)
{
    long long n4 = n >> 2;
    split_h_k<<<(unsigned)((n4 + 255) / 256), 256, 0, st>>>(
        (const float4*)in, (__half2*)hi, (__half2*)lo, n4);
}

// attn@V for one batch's 16 heads, permuted epilogue into [T, H*VHD]
static void attnv_s(cudaStream_t st, const __half* at, const __half* vT, __half* y2)
{
    dim3 grid(1, CT / 128, CH);
    gemm_h<1,128,1><<<grid, 512, SM_1_128, st>>>(
        at, nullptr, CT, (long long)CT*CT,
        vT, nullptr, CT, (long long)CVHD*CT,
        y2, CD, 0, CH, (long long)CVHD,
        nullptr, 0, 0, CT, CVHD, CT, 1.f, 2);
}

// streams/events created ONCE (first call = correctness run, before the
// harness's pre-capture memory baseline) and reused by every capture call.
static cudaStream_t g_s1 = nullptr, g_s2 = nullptr;
static cudaEvent_t  g_evFork, g_evQKA, g_evQB, g_evKB, g_evConv, g_evQKVA, g_evKV,
                    g_evSc0, g_evAt0;

extern "C" void kernel_launch(void* const* d_in, const int* in_sizes, int n_in,
                              void* d_out, int out_size)
{
    const float* x     = (const float*)d_in[0];
    const float* fcos  = (const float*)d_in[2];
    const float* fsin  = (const float*)d_in[3];
    const float* anw   = (const float*)d_in[4];
    const float* wq_a  = (const float*)d_in[5];
    const float* qnw   = (const float*)d_in[6];
    const float* wq_b  = (const float*)d_in[7];
    const float* wkv_a = (const float*)d_in[8];
    const float* kvnw  = (const float*)d_in[9];
    const float* wkv_b = (const float*)d_in[10];
    const float* wo    = (const float*)d_in[11];
    const float* fnw   = (const float*)d_in[12];
    const float* w1    = (const float*)d_in[13];
    const float* w2    = (const float*)d_in[14];
    const float* w3    = (const float*)d_in[15];
    float* out = (float*)d_out;

    if (!g_s1) {
        cudaStreamCreateWithFlags(&g_s1, cudaStreamNonBlocking);
        cudaStreamCreateWithFlags(&g_s2, cudaStreamNonBlocking);
        cudaEventCreateWithFlags(&g_evFork, cudaEventDisableTiming);
        cudaEventCreateWithFlags(&g_evQKA,  cudaEventDisableTiming);
        cudaEventCreateWithFlags(&g_evQB,   cudaEventDisableTiming);
        cudaEventCreateWithFlags(&g_evKB,   cudaEventDisableTiming);
        cudaEventCreateWithFlags(&g_evConv, cudaEventDisableTiming);
        cudaEventCreateWithFlags(&g_evQKVA, cudaEventDisableTiming);
        cudaEventCreateWithFlags(&g_evKV,   cudaEventDisableTiming);
        cudaEventCreateWithFlags(&g_evSc0,  cudaEventDisableTiming);
        cudaEventCreateWithFlags(&g_evAt0,  cudaEventDisableTiming);
        cudaFuncSetAttribute(gemm_h<3,128,0>, cudaFuncAttributeMaxDynamicSharedMemorySize, SM_3_128);
        cudaFuncSetAttribute(gemm_h<1,256,0>, cudaFuncAttributeMaxDynamicSharedMemorySize, SM_1_256);
        cudaFuncSetAttribute(gemm_h<1,128,0>, cudaFuncAttributeMaxDynamicSharedMemorySize, SM_1_128);
        cudaFuncSetAttribute(gemm_h<1,128,1>, cudaFuncAttributeMaxDynamicSharedMemorySize, SM_1_128);
        cudaFuncSetAttribute(gemm_h<1,256,2>, cudaFuncAttributeMaxDynamicSharedMemorySize, SM_1_256);
    }
    cudaStream_t s1 = g_s1, s2 = g_s2;

    float *p_qkva, *p_q, *p_kv, *p_sc, *p_x2;
    cudaGetSymbolAddress((void**)&p_qkva, g_qkva);
    cudaGetSymbolAddress((void**)&p_q,    g_q);
    cudaGetSymbolAddress((void**)&p_kv,   g_kv);
    cudaGetSymbolAddress((void**)&p_sc,   g_sc);
    cudaGetSymbolAddress((void**)&p_x2,   g_x2);

    __half *hH,*hL,*qaH,*qaL,*kvnH,*kvnL,*qfH,*qfL,*kfH,*kfL,*vT,*at,*y2,*h2,*gs,
           *wqkaH,*wqkaL,*wqbH,*wqbL,*wkbH,*wkbL,*woh,*w13h,*w2h;
    cudaGetSymbolAddress((void**)&hH,   f_hH);  cudaGetSymbolAddress((void**)&hL,   f_hL);
    cudaGetSymbolAddress((void**)&qaH,  f_qaH); cudaGetSymbolAddress((void**)&qaL,  f_qaL);
    cudaGetSymbolAddress((void**)&kvnH, f_kvnH);cudaGetSymbolAddress((void**)&kvnL, f_kvnL);
    cudaGetSymbolAddress((void**)&qfH,  f_qfH); cudaGetSymbolAddress((void**)&qfL,  f_qfL);
    cudaGetSymbolAddress((void**)&kfH,  f_kfH); cudaGetSymbolAddress((void**)&kfL,  f_kfL);
    cudaGetSymbolAddress((void**)&vT,   f_vT);  cudaGetSymbolAddress((void**)&at,   f_at);
    cudaGetSymbolAddress((void**)&y2,   f_y2);
    cudaGetSymbolAddress((void**)&h2,   f_h2);  cudaGetSymbolAddress((void**)&gs,   f_gs);
    cudaGetSymbolAddress((void**)&wqkaH,f_wqkaH);cudaGetSymbolAddress((void**)&wqkaL,f_wqkaL);
    cudaGetSymbolAddress((void**)&wqbH, f_wqbH);cudaGetSymbolAddress((void**)&wqbL, f_wqbL);
    cudaGetSymbolAddress((void**)&wkbH, f_wkbH);cudaGetSymbolAddress((void**)&wkbL, f_wkbL);
    cudaGetSymbolAddress((void**)&woh,  f_wo);
    cudaGetSymbolAddress((void**)&w13h, f_w13); cudaGetSymbolAddress((void**)&w2h,  f_w2);

    cudaEventRecord(g_evFork, 0);
    cudaStreamWaitEvent(s1, g_evFork, 0);

    // s1: weight conversions
    splitp_s(s1, wq_a,  wqkaH, wqkaL, (long long)CQLORA*CD);
    splitp_s(s1, wkv_a, wqkaH + (long long)CQLORA*CD, wqkaL + (long long)CQLORA*CD,
             (long long)(CKVLORA+CROPE)*CD);
    cudaEventRecord(g_evQKA, s1);
    splitp_s(s1, wq_b, wqbH, wqbL, (long long)CH*CQKD*CQLORA);
    cudaEventRecord(g_evQB, s1);
    splitp_s(s1, wkv_b, wkbH, wkbL, (long long)CH*256*CKVLORA);
    cudaEventRecord(g_evKB, s1);
    {
        long long n4big = ((long long)CINTER * CD) >> 2;
        long long n4wo  = ((long long)CD * CD) >> 2;
        dim3 grid((unsigned)((n4big + 255) / 256), 4);
        conv4_h_k<<<grid, 256, 0, s1>>>((const float4*)w1, (const float4*)w3,
                                        (const float4*)w2, (const float4*)wo,
                                        (__half2*)w13h, (__half2*)w2h, (__half2*)woh,
                                        n4big, n4wo);
    }
    cudaEventRecord(g_evConv, s1);

    // ---- main stream: attention path ----
    rmsnorm_split_h_k<<<CM, 256>>>(x, CD, anw, hH, hL, CD);
    cudaStreamWaitEvent(0, g_evQKA, 0);
    gemm3_s(0, hH, hL, CD, 0, wqkaH, wqkaL, CD, 0, p_qkva, NQKVA, 0,
            nullptr, 0, 0, CM, NQKVA, CD, 1.f, 1);
    cudaEventRecord(g_evQKVA, 0);

    // s2: kv path (norm + kv GEMM) in parallel with main's q path
    cudaStreamWaitEvent(s2, g_evQKVA, 0);
    cudaStreamWaitEvent(s2, g_evKB, 0);
    rmsnorm_split_h_k<<<CM, 256, 0, s2>>>(p_qkva + CQLORA, NQKVA, kvnw, kvnH, kvnL, CKVLORA);
    gemm3_s(s2, kvnH, kvnL, CKVLORA, 0, wkbH, wkbL, CKVLORA, 0, p_kv, CH*256, 0,
            nullptr, 0, 0, CM, CH*256, CKVLORA, 1.f, 1);
    cudaEventRecord(g_evKV, s2);

    // main: q path
    rmsnorm_split_h_k<<<CM, 256>>>(p_qkva, NQKVA, qnw, qaH, qaL, CQLORA);
    cudaStreamWaitEvent(0, g_evQB, 0);
    gemm3_s(0, qaH, qaL, CQLORA, 0, wqbH, wqbL, CQLORA, 0, p_q, CH*CQKD, 0,
            nullptr, 0, 0, CM, CH*CQKD, CQLORA, 1.f, 1);

    // join kv path, then rope
    cudaStreamWaitEvent(0, g_evKV, 0);
    rope_pack_h_k<<<dim3(CT, CB), 256>>>(p_q, p_kv, p_qkva, fcos, fsin,
                                         qfH, qfL, kfH, kfL, vT);

    // ---- attention core, pipelined per batch (16 heads each) ----
    const long long zQK = (long long)CH*CT*CQKD;
    const long long zSC = (long long)CH*CT*CT;
    const long long zV  = (long long)CH*CVHD*CT;

    // batch 0 scores (maskless; softmax handles boundary exactly)
    gemm3_s(0, qfH, qfL, CQKD, (long long)CT*CQKD,
            kfH, kfL, CQKD, (long long)CT*CQKD,
            p_sc, CT, (long long)CT*CT,
            nullptr, 0, 0, CT, CT, CQKD, -96.f, CH, 1);
    cudaEventRecord(g_evSc0, 0);

    // s2: softmax + attn@V for batch 0, overlapping batch 1 scores
    cudaStreamWaitEvent(s2, g_evSc0, 0);
    softmax_causal_h_k<<<CH*CT, 256, 0, s2>>>(p_sc, at);
    attnv_s(s2, at, vT, y2);
    cudaEventRecord(g_evAt0, s2);

    // main: batch 1 scores + softmax + attn@V
    gemm3_s(0, qfH + zQK, qfL + zQK, CQKD, (long long)CT*CQKD,
            kfH + zQK, kfL + zQK, CQKD, (long long)CT*CQKD,
            p_sc + zSC, CT, (long long)CT*CT,
            nullptr, 0, 0, CT, CT, CQKD, -96.f, CH, 1);
    softmax_causal_h_k<<<CH*CT, 256>>>(p_sc + zSC, at + zSC);
    attnv_s(0, at + zSC, vT + zV, y2 + (long long)CT*CD);

    // join batch-0 attn@V and conversions, then wo
    cudaStreamWaitEvent(0, g_evAt0, 0);
    cudaStreamWaitEvent(0, g_evConv, 0);
    gemm1f(y2, CH*CVHD, 0, woh, CH*CVHD, 0, p_x2, CD, 0,
           x, CD, 0, CM, CD, CH*CVHD, 1.f, 1);

    // ---- FFN path ----
    rmsnorm_h_k<<<CM, 256>>>(p_x2, CD, fnw, h2, CD);
    {
        dim3 grid((2*CINTER) / 256, CM / 128, 1);
        gemm_h<1,256,2><<<grid, 512, SM_1_256>>>(
            h2, nullptr, CD, 0,
            w13h, nullptr, CD, 0,
            gs, CINTER, 0, 1, 0,
            nullptr, 0, 0, CM, 2*CINTER, CD, 1.f, 0);
    }
    gemm1f(gs, CINTER, 0, w2h, CINTER, 0, out, CD, 0,
           p_x2, CD, 0, CM, CD, CINTER, 1.f, 1);
}